// round 3
// baseline (speedup 1.0000x reference)
#include <cuda_runtime.h>
#include <cuda_bf16.h>
#include <math.h>

// Problem constants (fixed by the dataset)
#define Bc    8
#define Nc    9856
#define Dc    256
#define HEADS 8
#define HD    32
#define WH    7
#define WW    11
#define L77   77
#define HIDc  512
#define Hc    56
#define Wc    176
#define NH    8
#define NWn   16
#define MROWS (Bc * Nc)       // 78848
#define NWIN  (Bc * NH * NWn) // 1024

// ---------------------------------------------------------------------------
// Scratch
// ---------------------------------------------------------------------------
__device__ float g_xn[(size_t)MROWS * Dc];
__device__ float g_qkv[(size_t)MROWS * 3 * Dc];   // later reused as [yn | hmid]
__device__ float g_y[(size_t)MROWS * Dc];

// ---------------------------------------------------------------------------
// LayerNorm: one warp per row of 256
// ---------------------------------------------------------------------------
__global__ void __launch_bounds__(256) ln_kernel(const float* __restrict__ x,
                                                 const float* __restrict__ g,
                                                 const float* __restrict__ b,
                                                 float* __restrict__ out)
{
    int warp = threadIdx.x >> 5, lane = threadIdx.x & 31;
    size_t row = (size_t)blockIdx.x * 8 + warp;
    const float* xr = x + row * Dc;
    int c = lane * 8;
    float4 v0 = *(const float4*)(xr + c);
    float4 v1 = *(const float4*)(xr + c + 4);
    float sum = v0.x + v0.y + v0.z + v0.w + v1.x + v1.y + v1.z + v1.w;
    float sq  = v0.x*v0.x + v0.y*v0.y + v0.z*v0.z + v0.w*v0.w
              + v1.x*v1.x + v1.y*v1.y + v1.z*v1.z + v1.w*v1.w;
    #pragma unroll
    for (int off = 16; off; off >>= 1) {
        sum += __shfl_xor_sync(0xffffffff, sum, off);
        sq  += __shfl_xor_sync(0xffffffff, sq,  off);
    }
    float mu  = sum * (1.0f / 256.0f);
    float var = sq * (1.0f / 256.0f) - mu * mu;
    float rs  = rsqrtf(var + 1e-5f);
    float4 g0 = *(const float4*)(g + c), g1 = *(const float4*)(g + c + 4);
    float4 b0 = *(const float4*)(b + c), b1 = *(const float4*)(b + c + 4);
    float4 o0, o1;
    o0.x = (v0.x - mu) * rs * g0.x + b0.x;  o0.y = (v0.y - mu) * rs * g0.y + b0.y;
    o0.z = (v0.z - mu) * rs * g0.z + b0.z;  o0.w = (v0.w - mu) * rs * g0.w + b0.w;
    o1.x = (v1.x - mu) * rs * g1.x + b1.x;  o1.y = (v1.y - mu) * rs * g1.y + b1.y;
    o1.z = (v1.z - mu) * rs * g1.z + b1.z;  o1.w = (v1.w - mu) * rs * g1.w + b1.w;
    *(float4*)(out + row * Dc + c)     = o0;
    *(float4*)(out + row * Dc + c + 4) = o1;
}

// ---------------------------------------------------------------------------
// tf32 tensor-core GEMM: C[M,N] = A[M,K] @ B[N,K]^T + bias (+epilogue)
// CTA tile 128x128, BK=16, 8 warps, warp tile 64x32 (4x4 m16n8k8 mma).
// Smem layout: permuted K (perm(k)=(k%4)*4+k/4) so each thread's fragment
// columns {t,t+4,t+8,t+12} are one contiguous quad, plus quad-XOR swizzle
// (quad ^ (row&3)) for conflict-free LDS.128. Double-buffered, 1 sync/tile.
// EPI 0: bias; 1: bias+GELU; 2: bias+residual
// ---------------------------------------------------------------------------
__device__ __forceinline__ unsigned f2tf32(float f)
{
    unsigned r;
    asm("cvt.rna.tf32.f32 %0, %1;" : "=r"(r) : "f"(f));
    return r;
}

__device__ __forceinline__ void mma_tf32(float (&c)[4], unsigned a0, unsigned a1,
                                         unsigned a2, unsigned a3,
                                         unsigned b0, unsigned b1)
{
    asm volatile(
        "mma.sync.aligned.m16n8k8.row.col.f32.tf32.tf32.f32 "
        "{%0,%1,%2,%3}, {%4,%5,%6,%7}, {%8,%9}, {%0,%1,%2,%3};"
        : "+f"(c[0]), "+f"(c[1]), "+f"(c[2]), "+f"(c[3])
        : "r"(a0), "r"(a1), "r"(a2), "r"(a3), "r"(b0), "r"(b1));
}

__device__ __forceinline__ float gelu_exact(float v)
{
    return 0.5f * v * (1.0f + erff(v * 0.70710678118654752f));
}

template <int EPI>
__global__ void __launch_bounds__(256, 2) tgemm_kernel(const float* __restrict__ A,
                                                       const float* __restrict__ B,
                                                       const float* __restrict__ bias,
                                                       const float* __restrict__ resid,
                                                       float* __restrict__ C,
                                                       int M, int N, int K)
{
    __shared__ unsigned As[2][128][16];
    __shared__ unsigned Bs[2][128][16];

    int tid  = threadIdx.x;
    int lane = tid & 31, warp = tid >> 5;
    int wm = warp >> 2, wn = warp & 3;       // 2 x 4 warp grid
    int g = lane >> 2, t = lane & 3;
    int m0 = blockIdx.y * 128, n0 = blockIdx.x * 128;

    float acc[4][4][4] = {};

    int lr = tid >> 2;           // 0..63
    int t4 = tid & 3;
    int lc = t4 << 2;            // 0,4,8,12
    int sw = lr & 3;             // swizzle key for stores
    const float* Ag0 = A + (size_t)(m0 + lr) * K + lc;
    const float* Ag1 = Ag0 + (size_t)64 * K;
    const float* Bg0 = B + (size_t)(n0 + lr) * K + lc;
    const float* Bg1 = Bg0 + (size_t)64 * K;

#define STS_TILE(bufi, A0, A1, B0, B1)                                         \
    do {                                                                       \
        float a0w[4] = {A0.x, A0.y, A0.z, A0.w};                               \
        float a1w[4] = {A1.x, A1.y, A1.z, A1.w};                               \
        float b0w[4] = {B0.x, B0.y, B0.z, B0.w};                               \
        float b1w[4] = {B1.x, B1.y, B1.z, B1.w};                               \
        _Pragma("unroll")                                                      \
        for (int j = 0; j < 4; j++) {                                          \
            int wofs = ((j ^ sw) << 2) | t4;                                   \
            As[bufi][lr][wofs]      = f2tf32(a0w[j]);                          \
            As[bufi][lr + 64][wofs] = f2tf32(a1w[j]);                          \
            Bs[bufi][lr][wofs]      = f2tf32(b0w[j]);                          \
            Bs[bufi][lr + 64][wofs] = f2tf32(b1w[j]);                          \
        }                                                                      \
    } while (0)

    float4 pa0 = *(const float4*)(Ag0);
    float4 pa1 = *(const float4*)(Ag1);
    float4 pb0 = *(const float4*)(Bg0);
    float4 pb1 = *(const float4*)(Bg1);
    STS_TILE(0, pa0, pa1, pb0, pb1);
    __syncthreads();

    int ktiles = K >> 4;
    int buf = 0;
    for (int kt = 0; kt < ktiles; kt++) {
        bool more = (kt + 1 < ktiles);
        if (more) {
            int off = (kt + 1) << 4;
            pa0 = *(const float4*)(Ag0 + off);
            pa1 = *(const float4*)(Ag1 + off);
            pb0 = *(const float4*)(Bg0 + off);
            pb1 = *(const float4*)(Bg1 + off);
        }

        // B fragments: quad t of row (wn*32 + nt*8 + g), swizzled
        uint4 bq[4];
        #pragma unroll
        for (int nt = 0; nt < 4; nt++) {
            int r = wn * 32 + nt * 8 + g;
            bq[nt] = *(const uint4*)&Bs[buf][r][(t ^ (r & 3)) << 2];
        }
        #pragma unroll
        for (int mt = 0; mt < 4; mt++) {
            int r0 = wm * 64 + mt * 16 + g;
            int r1 = r0 + 8;
            uint4 a0 = *(const uint4*)&As[buf][r0][(t ^ (r0 & 3)) << 2];
            uint4 a1 = *(const uint4*)&As[buf][r1][(t ^ (r1 & 3)) << 2];
            #pragma unroll
            for (int nt = 0; nt < 4; nt++) {
                // kk = 0 : A cols {t, t+4} -> (x, y); B cols {t, t+4} -> (x, y)
                mma_tf32(acc[mt][nt], a0.x, a1.x, a0.y, a1.y, bq[nt].x, bq[nt].y);
                // kk = 8 : A cols {t+8, t+12} -> (z, w)
                mma_tf32(acc[mt][nt], a0.z, a1.z, a0.w, a1.w, bq[nt].z, bq[nt].w);
            }
        }

        if (more) STS_TILE(buf ^ 1, pa0, pa1, pb0, pb1);
        __syncthreads();
        buf ^= 1;
    }
#undef STS_TILE

    // Epilogue: c0,c1 -> (row g, cols 2t,2t+1); c2,c3 -> (row g+8)
    #pragma unroll
    for (int mt = 0; mt < 4; mt++) {
        size_t r0 = (size_t)m0 + wm * 64 + mt * 16 + g;
        size_t r1 = r0 + 8;
        #pragma unroll
        for (int nt = 0; nt < 4; nt++) {
            int col = n0 + wn * 32 + nt * 8 + 2 * t;
            float b0 = bias[col], b1 = bias[col + 1];
            float v00 = acc[mt][nt][0] + b0, v01 = acc[mt][nt][1] + b1;
            float v10 = acc[mt][nt][2] + b0, v11 = acc[mt][nt][3] + b1;
            if (EPI == 1) {
                v00 = gelu_exact(v00); v01 = gelu_exact(v01);
                v10 = gelu_exact(v10); v11 = gelu_exact(v11);
            }
            if (EPI == 2) {
                float2 q0 = *(const float2*)&resid[r0 * N + col];
                float2 q1 = *(const float2*)&resid[r1 * N + col];
                v00 += q0.x; v01 += q0.y; v10 += q1.x; v11 += q1.y;
            }
            *(float2*)&C[r0 * N + col] = make_float2(v00, v01);
            *(float2*)&C[r1 * N + col] = make_float2(v10, v11);
        }
    }
}

// ---------------------------------------------------------------------------
// Windowed attention: one CTA per (window, head); 2 query rows per warp pass
// ---------------------------------------------------------------------------
__device__ __forceinline__ int rowmap(int wi, int l)
{
    int b   = wi >> 7;
    int rem = wi & 127;
    int hb  = rem >> 4;
    int wb  = rem & 15;
    int r   = l / WW;
    int c   = l - r * WW;
    return b * Nc + (hb * WH + r) * Wc + wb * WW + c;
}

__global__ void __launch_bounds__(256) attn_kernel(const float* __restrict__ qkv,
                                                   float* __restrict__ o)
{
    __shared__ float sQ[L77 * 36];
    __shared__ float sK[L77 * 36];
    __shared__ float sV[L77 * 36];
    __shared__ float sP[16][80];

    int bx = blockIdx.x;
    int wi = bx >> 3, h = bx & 7;
    int tid = threadIdx.x, lane = tid & 31, w = tid >> 5;

    for (int idx = tid; idx < L77 * HD; idx += 256) {
        int l = idx >> 5, d = idx & 31;
        int grow = rowmap(wi, l);
        const float* base = qkv + (size_t)grow * (3 * Dc) + h * HD + d;
        sQ[l * 36 + d] = base[0];
        sK[l * 36 + d] = base[Dc];
        sV[l * 36 + d] = base[2 * Dc];
    }
    __syncthreads();

    const float scale = 0.17677669529663687f;  // 1/sqrt(32)
    bool v2 = (lane < 13);                     // lane+64 < 77
    int pr = w * 2;

    for (int r = 0; r < 5; r++) {
        int ia = 2 * w + 16 * r;
        if (ia >= L77) break;
        bool hb = (ia + 1 < L77);
        int ib = hb ? ia + 1 : ia;

        const float4* qa4 = (const float4*)&sQ[ia * 36];
        const float4* qb4 = (const float4*)&sQ[ib * 36];

        float sa0 = 0.f, sa1 = 0.f, sa2 = 0.f;
        float sb0 = 0.f, sb1 = 0.f, sb2 = 0.f;
        #pragma unroll
        for (int d4 = 0; d4 < 8; d4++) {
            float4 k0 = *(const float4*)&sK[lane * 36 + d4 * 4];
            float4 k1 = *(const float4*)&sK[(lane + 32) * 36 + d4 * 4];
            float4 qa = qa4[d4];
            float4 qb = qb4[d4];
            sa0 += qa.x*k0.x + qa.y*k0.y + qa.z*k0.z + qa.w*k0.w;
            sa1 += qa.x*k1.x + qa.y*k1.y + qa.z*k1.z + qa.w*k1.w;
            sb0 += qb.x*k0.x + qb.y*k0.y + qb.z*k0.z + qb.w*k0.w;
            sb1 += qb.x*k1.x + qb.y*k1.y + qb.z*k1.z + qb.w*k1.w;
            if (v2) {
                float4 k2 = *(const float4*)&sK[(lane + 64) * 36 + d4 * 4];
                sa2 += qa.x*k2.x + qa.y*k2.y + qa.z*k2.z + qa.w*k2.w;
                sb2 += qb.x*k2.x + qb.y*k2.y + qb.z*k2.z + qb.w*k2.w;
            }
        }
        sa0 *= scale; sa1 *= scale; sb0 *= scale; sb1 *= scale;
        sa2 = v2 ? sa2 * scale : -1e30f;
        sb2 = v2 ? sb2 * scale : -1e30f;

        float mxa = fmaxf(sa0, fmaxf(sa1, sa2));
        float mxb = fmaxf(sb0, fmaxf(sb1, sb2));
        #pragma unroll
        for (int off = 16; off; off >>= 1) {
            mxa = fmaxf(mxa, __shfl_xor_sync(0xffffffff, mxa, off));
            mxb = fmaxf(mxb, __shfl_xor_sync(0xffffffff, mxb, off));
        }
        float ea0 = __expf(sa0 - mxa), ea1 = __expf(sa1 - mxa);
        float ea2 = v2 ? __expf(sa2 - mxa) : 0.f;
        float eb0 = __expf(sb0 - mxb), eb1 = __expf(sb1 - mxb);
        float eb2 = v2 ? __expf(sb2 - mxb) : 0.f;
        float suma = ea0 + ea1 + ea2;
        float sumb = eb0 + eb1 + eb2;
        #pragma unroll
        for (int off = 16; off; off >>= 1) {
            suma += __shfl_xor_sync(0xffffffff, suma, off);
            sumb += __shfl_xor_sync(0xffffffff, sumb, off);
        }
        float inva = 1.0f / suma, invb = 1.0f / sumb;
        sP[pr][lane]      = ea0 * inva;
        sP[pr][lane + 32] = ea1 * inva;
        if (v2) sP[pr][lane + 64] = ea2 * inva;
        sP[pr + 1][lane]      = eb0 * invb;
        sP[pr + 1][lane + 32] = eb1 * invb;
        if (v2) sP[pr + 1][lane + 64] = eb2 * invb;
        __syncwarp();

        float acca = 0.f, accb = 0.f;
        #pragma unroll 7
        for (int j = 0; j < L77; j++) {
            float vv = sV[j * 36 + lane];
            acca += sP[pr][j] * vv;
            accb += sP[pr + 1][j] * vv;
        }
        int growa = rowmap(wi, ia);
        o[(size_t)growa * Dc + h * HD + lane] = acca;
        if (hb) {
            int growb = rowmap(wi, ib);
            o[(size_t)growb * Dc + h * HD + lane] = accb;
        }
        __syncwarp();
    }
}

// ---------------------------------------------------------------------------
// Launch
// ---------------------------------------------------------------------------
extern "C" void kernel_launch(void* const* d_in, const int* in_sizes, int n_in,
                              void* d_out, int out_size)
{
    const float* x         = (const float*)d_in[0];
    const float* norm1_g   = (const float*)d_in[1];
    const float* norm1_b   = (const float*)d_in[2];
    const float* in_proj_w = (const float*)d_in[3];
    const float* in_proj_b = (const float*)d_in[4];
    const float* out_w     = (const float*)d_in[5];
    const float* out_b     = (const float*)d_in[6];
    const float* norm2_g   = (const float*)d_in[7];
    const float* norm2_b   = (const float*)d_in[8];
    const float* fc1_w     = (const float*)d_in[9];
    const float* fc1_b     = (const float*)d_in[10];
    const float* fc2_w     = (const float*)d_in[11];
    const float* fc2_b     = (const float*)d_in[12];
    float* out = (float*)d_out;

    float *p_xn, *p_qkv, *p_y;
    cudaGetSymbolAddress((void**)&p_xn,  g_xn);
    cudaGetSymbolAddress((void**)&p_qkv, g_qkv);
    cudaGetSymbolAddress((void**)&p_y,   g_y);

    // 1) LN1
    ln_kernel<<<MROWS / 8, 256>>>(x, norm1_g, norm1_b, p_xn);

    // 2) QKV = xn @ in_proj_w^T + b
    {
        dim3 grid(768 / 128, MROWS / 128);
        tgemm_kernel<0><<<grid, 256>>>(p_xn, in_proj_w, in_proj_b, nullptr,
                                       p_qkv, MROWS, 3 * Dc, Dc);
    }

    // 3) attention -> o (reuse g_xn)
    attn_kernel<<<NWIN * HEADS, 256>>>(p_qkv, p_xn);

    // 4) y = x + o @ out_w^T + out_b
    {
        dim3 grid(Dc / 128, MROWS / 128);
        tgemm_kernel<2><<<grid, 256>>>(p_xn, out_w, out_b, x, p_y,
                                       MROWS, Dc, Dc);
    }

    // 5) LN2: y -> yn (in g_qkv[0:M*256))
    ln_kernel<<<MROWS / 8, 256>>>(p_y, norm2_g, norm2_b, p_qkv);

    // 6) hmid = gelu(yn @ fc1_w^T + fc1_b)
    float* p_yn   = p_qkv;
    float* p_hmid = p_qkv + (size_t)MROWS * Dc;
    {
        dim3 grid(HIDc / 128, MROWS / 128);
        tgemm_kernel<1><<<grid, 256>>>(p_yn, fc1_w, fc1_b, nullptr, p_hmid,
                                       MROWS, HIDc, Dc);
    }

    // 7) out = y + hmid @ fc2_w^T + fc2_b
    {
        dim3 grid(Dc / 128, MROWS / 128);
        tgemm_kernel<2><<<grid, 256>>>(p_hmid, fc2_w, fc2_b, p_y, out,
                                       MROWS, Dc, HIDc);
    }
}

// round 4
// speedup vs baseline: 1.4174x; 1.4174x over previous
#include <cuda_runtime.h>
#include <cuda_bf16.h>
#include <math.h>
#include <stdint.h>

// Problem constants
#define Bc    8
#define Nc    9856
#define Dc    256
#define HEADS 8
#define HD    32
#define WH    7
#define WW    11
#define L77   77
#define HIDc  512
#define Hc    56
#define Wc    176
#define NH    8
#define NWn   16
#define MROWS (Bc * Nc)       // 78848
#define NWIN  (Bc * NH * NWn) // 1024

// ---------------------------------------------------------------------------
// Scratch (device globals)
// ---------------------------------------------------------------------------
__device__ __nv_bfloat16 g_xnb[(size_t)MROWS * Dc];        // xn, later attn out o
__device__ __nv_bfloat16 g_qkvb[(size_t)MROWS * 3 * Dc];   // qkv, later [yn | hmid]
__device__ float         g_y[(size_t)MROWS * Dc];          // x + attn residual
__device__ __nv_bfloat16 g_wqkv[3 * Dc * Dc];
__device__ __nv_bfloat16 g_wout[Dc * Dc];
__device__ __nv_bfloat16 g_wfc1[HIDc * Dc];
__device__ __nv_bfloat16 g_wfc2[Dc * HIDc];

// ---------------------------------------------------------------------------
// fp32 -> bf16 weight conversion
// ---------------------------------------------------------------------------
__global__ void __launch_bounds__(256) f2bf_kernel(const float* __restrict__ in,
                                                   __nv_bfloat16* __restrict__ out,
                                                   int n)
{
    int i = (blockIdx.x * 256 + threadIdx.x) * 4;
    if (i < n) {
        float4 v = *(const float4*)(in + i);
        union { __nv_bfloat162 h[2]; uint2 u; } pk;
        pk.h[0] = __float22bfloat162_rn(make_float2(v.x, v.y));
        pk.h[1] = __float22bfloat162_rn(make_float2(v.z, v.w));
        *(uint2*)(out + i) = pk.u;
    }
}

// ---------------------------------------------------------------------------
// LayerNorm: one warp per row of 256, bf16 output
// ---------------------------------------------------------------------------
__global__ void __launch_bounds__(256) ln_bf_kernel(const float* __restrict__ x,
                                                    const float* __restrict__ g,
                                                    const float* __restrict__ b,
                                                    __nv_bfloat16* __restrict__ out)
{
    int warp = threadIdx.x >> 5, lane = threadIdx.x & 31;
    size_t row = (size_t)blockIdx.x * 8 + warp;
    const float* xr = x + row * Dc;
    int c = lane * 8;
    float4 v0 = *(const float4*)(xr + c);
    float4 v1 = *(const float4*)(xr + c + 4);
    float sum = v0.x + v0.y + v0.z + v0.w + v1.x + v1.y + v1.z + v1.w;
    float sq  = v0.x*v0.x + v0.y*v0.y + v0.z*v0.z + v0.w*v0.w
              + v1.x*v1.x + v1.y*v1.y + v1.z*v1.z + v1.w*v1.w;
    #pragma unroll
    for (int off = 16; off; off >>= 1) {
        sum += __shfl_xor_sync(0xffffffff, sum, off);
        sq  += __shfl_xor_sync(0xffffffff, sq,  off);
    }
    float mu  = sum * (1.0f / 256.0f);
    float var = sq * (1.0f / 256.0f) - mu * mu;
    float rs  = rsqrtf(var + 1e-5f);
    float4 g0 = *(const float4*)(g + c), g1 = *(const float4*)(g + c + 4);
    float4 b0 = *(const float4*)(b + c), b1 = *(const float4*)(b + c + 4);
    union { __nv_bfloat162 h[4]; uint4 u; } pk;
    pk.h[0] = __float22bfloat162_rn(make_float2((v0.x - mu) * rs * g0.x + b0.x,
                                                (v0.y - mu) * rs * g0.y + b0.y));
    pk.h[1] = __float22bfloat162_rn(make_float2((v0.z - mu) * rs * g0.z + b0.z,
                                                (v0.w - mu) * rs * g0.w + b0.w));
    pk.h[2] = __float22bfloat162_rn(make_float2((v1.x - mu) * rs * g1.x + b1.x,
                                                (v1.y - mu) * rs * g1.y + b1.y));
    pk.h[3] = __float22bfloat162_rn(make_float2((v1.z - mu) * rs * g1.z + b1.z,
                                                (v1.w - mu) * rs * g1.w + b1.w));
    *(uint4*)(out + row * Dc + c) = pk.u;
}

// ---------------------------------------------------------------------------
// bf16 tensor-core GEMM: C[M,N] = A[M,K] @ B[N,K]^T + bias (+epilogue)
// CTA 128x128, BK=32, 8 warps (2x4), warp tile 64x32, m16n8k16 mma.
// cp.async double-buffered smem (pitch 40 bf16 rows -> conflict-free ldmatrix).
// EPI 0: bias; 1: bias+GELU; 2: bias+residual.  OBF: bf16 vs fp32 output.
// ---------------------------------------------------------------------------
__device__ __forceinline__ void cp16(uint32_t saddr, const void* g)
{
    asm volatile("cp.async.cg.shared.global [%0], [%1], 16;\n"
                 :: "r"(saddr), "l"(g));
}

__device__ __forceinline__ void ldsm4(uint32_t* r, uint32_t addr)
{
    asm volatile("ldmatrix.sync.aligned.m8n8.x4.shared.b16 {%0,%1,%2,%3}, [%4];"
                 : "=r"(r[0]), "=r"(r[1]), "=r"(r[2]), "=r"(r[3]) : "r"(addr));
}

__device__ __forceinline__ void mma_bf16(float (&c)[4], const uint32_t* a,
                                         uint32_t b0, uint32_t b1)
{
    asm volatile(
        "mma.sync.aligned.m16n8k16.row.col.f32.bf16.bf16.f32 "
        "{%0,%1,%2,%3}, {%4,%5,%6,%7}, {%8,%9}, {%0,%1,%2,%3};"
        : "+f"(c[0]), "+f"(c[1]), "+f"(c[2]), "+f"(c[3])
        : "r"(a[0]), "r"(a[1]), "r"(a[2]), "r"(a[3]), "r"(b0), "r"(b1));
}

__device__ __forceinline__ float gelu_exact(float v)
{
    return 0.5f * v * (1.0f + erff(v * 0.70710678118654752f));
}

template <int EPI, int OBF>
__global__ void __launch_bounds__(256, 2) bgemm_kernel(const __nv_bfloat16* __restrict__ A,
                                                       const __nv_bfloat16* __restrict__ B,
                                                       const float* __restrict__ bias,
                                                       const float* __restrict__ resid,
                                                       void* __restrict__ Cv,
                                                       int M, int N, int K)
{
    __shared__ __nv_bfloat16 sA[2][128 * 40];
    __shared__ __nv_bfloat16 sB[2][128 * 40];
    const uint32_t STG = 128 * 40 * 2;  // bytes per stage (10240)

    int tid = threadIdx.x, lane = tid & 31, warp = tid >> 5;
    int wm = warp >> 2, wn = warp & 3;
    int m0 = blockIdx.y * 128, n0 = blockIdx.x * 128;

    // cp.async: each thread copies 2x16B (one 32B row segment) per matrix
    int srow = tid >> 1, scb = (tid & 1) * 2;
    const __nv_bfloat16* gA = A + (size_t)(m0 + srow) * K + scb * 8;
    const __nv_bfloat16* gB = B + (size_t)(n0 + srow) * K + scb * 8;
    uint32_t swA = (uint32_t)__cvta_generic_to_shared(&sA[0][srow * 40 + scb * 8]);
    uint32_t swB = (uint32_t)__cvta_generic_to_shared(&sB[0][srow * 40 + scb * 8]);

    // ldmatrix lane addressing
    int a_row = lane & 15;
    int a_c   = lane >> 4;            // 0/1 -> k chunk add
    int b_row = (lane & 7) | (((lane >> 4) & 1) << 3);
    int b_c   = (lane >> 3) & 1;
    uint32_t lA = (uint32_t)__cvta_generic_to_shared(&sA[0][(wm * 64 + a_row) * 40]);
    uint32_t lB = (uint32_t)__cvta_generic_to_shared(&sB[0][(wn * 32 + b_row) * 40]);

    float acc[4][4][4] = {};

    int ktiles = K >> 5;

    #pragma unroll
    for (int s = 0; s < 2; s++) {
        const __nv_bfloat16* ga = gA + s * 32;
        const __nv_bfloat16* gb = gB + s * 32;
        cp16(swA + s * STG,      ga);
        cp16(swA + s * STG + 16, ga + 8);
        cp16(swB + s * STG,      gb);
        cp16(swB + s * STG + 16, gb + 8);
        asm volatile("cp.async.commit_group;");
    }

    for (int kt = 0; kt < ktiles; kt++) {
        asm volatile("cp.async.wait_group 1;");
        __syncthreads();
        int buf = kt & 1;
        uint32_t aB = lA + buf * STG, bB = lB + buf * STG;
        #pragma unroll
        for (int kk = 0; kk < 2; kk++) {
            uint32_t a[4][4], b[2][4];
            #pragma unroll
            for (int mt = 0; mt < 4; mt++)
                ldsm4(a[mt], aB + mt * 1280 + (kk * 2 + a_c) * 16);
            #pragma unroll
            for (int p = 0; p < 2; p++)
                ldsm4(b[p], bB + p * 1280 + (kk * 2 + b_c) * 16);
            #pragma unroll
            for (int mt = 0; mt < 4; mt++) {
                mma_bf16(acc[mt][0], a[mt], b[0][0], b[0][1]);
                mma_bf16(acc[mt][1], a[mt], b[0][2], b[0][3]);
                mma_bf16(acc[mt][2], a[mt], b[1][0], b[1][1]);
                mma_bf16(acc[mt][3], a[mt], b[1][2], b[1][3]);
            }
        }
        __syncthreads();
        if (kt + 2 < ktiles) {
            const __nv_bfloat16* ga = gA + (kt + 2) * 32;
            const __nv_bfloat16* gb = gB + (kt + 2) * 32;
            cp16(swA + buf * STG,      ga);
            cp16(swA + buf * STG + 16, ga + 8);
            cp16(swB + buf * STG,      gb);
            cp16(swB + buf * STG + 16, gb + 8);
            asm volatile("cp.async.commit_group;");
        }
    }

    // Epilogue: c0,c1 -> (row g, cols 2t,2t+1); c2,c3 -> (row g+8)
    float* Cf = (float*)Cv;
    __nv_bfloat16* Cb = (__nv_bfloat16*)Cv;
    int g = lane >> 2, t = lane & 3;
    #pragma unroll
    for (int mt = 0; mt < 4; mt++) {
        size_t r0 = (size_t)m0 + wm * 64 + mt * 16 + g;
        size_t r1 = r0 + 8;
        #pragma unroll
        for (int nt = 0; nt < 4; nt++) {
            int col = n0 + wn * 32 + nt * 8 + 2 * t;
            float b0 = bias[col], b1 = bias[col + 1];
            float v00 = acc[mt][nt][0] + b0, v01 = acc[mt][nt][1] + b1;
            float v10 = acc[mt][nt][2] + b0, v11 = acc[mt][nt][3] + b1;
            if (EPI == 1) {
                v00 = gelu_exact(v00); v01 = gelu_exact(v01);
                v10 = gelu_exact(v10); v11 = gelu_exact(v11);
            }
            if (EPI == 2) {
                float2 q0 = *(const float2*)&resid[r0 * N + col];
                float2 q1 = *(const float2*)&resid[r1 * N + col];
                v00 += q0.x; v01 += q0.y; v10 += q1.x; v11 += q1.y;
            }
            if (OBF) {
                *(__nv_bfloat162*)&Cb[r0 * N + col] =
                    __float22bfloat162_rn(make_float2(v00, v01));
                *(__nv_bfloat162*)&Cb[r1 * N + col] =
                    __float22bfloat162_rn(make_float2(v10, v11));
            } else {
                *(float2*)&Cf[r0 * N + col] = make_float2(v00, v01);
                *(float2*)&Cf[r1 * N + col] = make_float2(v10, v11);
            }
        }
    }
}

// ---------------------------------------------------------------------------
// Windowed attention (bf16 qkv in, bf16 o out; fp32 compute in smem)
// ---------------------------------------------------------------------------
__device__ __forceinline__ int rowmap(int wi, int l)
{
    int b   = wi >> 7;
    int rem = wi & 127;
    int hb  = rem >> 4;
    int wb  = rem & 15;
    int r   = l / WW;
    int c   = l - r * WW;
    return b * Nc + (hb * WH + r) * Wc + wb * WW + c;
}

__global__ void __launch_bounds__(256) attn_kernel(const __nv_bfloat16* __restrict__ qkv,
                                                   __nv_bfloat16* __restrict__ o)
{
    __shared__ float sQ[L77 * 36];
    __shared__ float sK[L77 * 36];
    __shared__ float sV[L77 * 36];
    __shared__ float sP[16][80];

    int bx = blockIdx.x;
    int wi = bx >> 3, h = bx & 7;
    int tid = threadIdx.x, lane = tid & 31, w = tid >> 5;

    for (int idx = tid; idx < L77 * HD; idx += 256) {
        int l = idx >> 5, d = idx & 31;
        int grow = rowmap(wi, l);
        const __nv_bfloat16* base = qkv + (size_t)grow * (3 * Dc) + h * HD + d;
        sQ[l * 36 + d] = __bfloat162float(base[0]);
        sK[l * 36 + d] = __bfloat162float(base[Dc]);
        sV[l * 36 + d] = __bfloat162float(base[2 * Dc]);
    }
    __syncthreads();

    const float scale = 0.17677669529663687f;  // 1/sqrt(32)
    bool v2 = (lane < 13);
    int pr = w * 2;

    for (int r = 0; r < 5; r++) {
        int ia = 2 * w + 16 * r;
        if (ia >= L77) break;
        bool hb = (ia + 1 < L77);
        int ib = hb ? ia + 1 : ia;

        const float4* qa4 = (const float4*)&sQ[ia * 36];
        const float4* qb4 = (const float4*)&sQ[ib * 36];

        float sa0 = 0.f, sa1 = 0.f, sa2 = 0.f;
        float sb0 = 0.f, sb1 = 0.f, sb2 = 0.f;
        #pragma unroll
        for (int d4 = 0; d4 < 8; d4++) {
            float4 k0 = *(const float4*)&sK[lane * 36 + d4 * 4];
            float4 k1 = *(const float4*)&sK[(lane + 32) * 36 + d4 * 4];
            float4 qa = qa4[d4];
            float4 qb = qb4[d4];
            sa0 += qa.x*k0.x + qa.y*k0.y + qa.z*k0.z + qa.w*k0.w;
            sa1 += qa.x*k1.x + qa.y*k1.y + qa.z*k1.z + qa.w*k1.w;
            sb0 += qb.x*k0.x + qb.y*k0.y + qb.z*k0.z + qb.w*k0.w;
            sb1 += qb.x*k1.x + qb.y*k1.y + qb.z*k1.z + qb.w*k1.w;
            if (v2) {
                float4 k2 = *(const float4*)&sK[(lane + 64) * 36 + d4 * 4];
                sa2 += qa.x*k2.x + qa.y*k2.y + qa.z*k2.z + qa.w*k2.w;
                sb2 += qb.x*k2.x + qb.y*k2.y + qb.z*k2.z + qb.w*k2.w;
            }
        }
        sa0 *= scale; sa1 *= scale; sb0 *= scale; sb1 *= scale;
        sa2 = v2 ? sa2 * scale : -1e30f;
        sb2 = v2 ? sb2 * scale : -1e30f;

        float mxa = fmaxf(sa0, fmaxf(sa1, sa2));
        float mxb = fmaxf(sb0, fmaxf(sb1, sb2));
        #pragma unroll
        for (int off = 16; off; off >>= 1) {
            mxa = fmaxf(mxa, __shfl_xor_sync(0xffffffff, mxa, off));
            mxb = fmaxf(mxb, __shfl_xor_sync(0xffffffff, mxb, off));
        }
        float ea0 = __expf(sa0 - mxa), ea1 = __expf(sa1 - mxa);
        float ea2 = v2 ? __expf(sa2 - mxa) : 0.f;
        float eb0 = __expf(sb0 - mxb), eb1 = __expf(sb1 - mxb);
        float eb2 = v2 ? __expf(sb2 - mxb) : 0.f;
        float suma = ea0 + ea1 + ea2;
        float sumb = eb0 + eb1 + eb2;
        #pragma unroll
        for (int off = 16; off; off >>= 1) {
            suma += __shfl_xor_sync(0xffffffff, suma, off);
            sumb += __shfl_xor_sync(0xffffffff, sumb, off);
        }
        float inva = 1.0f / suma, invb = 1.0f / sumb;
        sP[pr][lane]      = ea0 * inva;
        sP[pr][lane + 32] = ea1 * inva;
        if (v2) sP[pr][lane + 64] = ea2 * inva;
        sP[pr + 1][lane]      = eb0 * invb;
        sP[pr + 1][lane + 32] = eb1 * invb;
        if (v2) sP[pr + 1][lane + 64] = eb2 * invb;
        __syncwarp();

        float acca = 0.f, accb = 0.f;
        #pragma unroll 7
        for (int j = 0; j < L77; j++) {
            float vv = sV[j * 36 + lane];
            acca += sP[pr][j] * vv;
            accb += sP[pr + 1][j] * vv;
        }
        int growa = rowmap(wi, ia);
        o[(size_t)growa * Dc + h * HD + lane] = __float2bfloat16(acca);
        if (hb) {
            int growb = rowmap(wi, ib);
            o[(size_t)growb * Dc + h * HD + lane] = __float2bfloat16(accb);
        }
        __syncwarp();
    }
}

// ---------------------------------------------------------------------------
// Launch
// ---------------------------------------------------------------------------
extern "C" void kernel_launch(void* const* d_in, const int* in_sizes, int n_in,
                              void* d_out, int out_size)
{
    const float* x         = (const float*)d_in[0];
    const float* norm1_g   = (const float*)d_in[1];
    const float* norm1_b   = (const float*)d_in[2];
    const float* in_proj_w = (const float*)d_in[3];
    const float* in_proj_b = (const float*)d_in[4];
    const float* out_w     = (const float*)d_in[5];
    const float* out_b     = (const float*)d_in[6];
    const float* norm2_g   = (const float*)d_in[7];
    const float* norm2_b   = (const float*)d_in[8];
    const float* fc1_w     = (const float*)d_in[9];
    const float* fc1_b     = (const float*)d_in[10];
    const float* fc2_w     = (const float*)d_in[11];
    const float* fc2_b     = (const float*)d_in[12];
    float* out = (float*)d_out;

    __nv_bfloat16 *p_xnb, *p_qkvb, *p_wqkv, *p_wout, *p_wfc1, *p_wfc2;
    float* p_y;
    cudaGetSymbolAddress((void**)&p_xnb,  g_xnb);
    cudaGetSymbolAddress((void**)&p_qkvb, g_qkvb);
    cudaGetSymbolAddress((void**)&p_y,    g_y);
    cudaGetSymbolAddress((void**)&p_wqkv, g_wqkv);
    cudaGetSymbolAddress((void**)&p_wout, g_wout);
    cudaGetSymbolAddress((void**)&p_wfc1, g_wfc1);
    cudaGetSymbolAddress((void**)&p_wfc2, g_wfc2);

    // 0) weight conversions fp32 -> bf16
    f2bf_kernel<<<(3 * Dc * Dc) / 1024, 256>>>(in_proj_w, p_wqkv, 3 * Dc * Dc);
    f2bf_kernel<<<(Dc * Dc) / 1024, 256>>>(out_w, p_wout, Dc * Dc);
    f2bf_kernel<<<(HIDc * Dc) / 1024, 256>>>(fc1_w, p_wfc1, HIDc * Dc);
    f2bf_kernel<<<(Dc * HIDc) / 1024, 256>>>(fc2_w, p_wfc2, Dc * HIDc);

    // 1) LN1: x -> xn (bf16)
    ln_bf_kernel<<<MROWS / 8, 256>>>(x, norm1_g, norm1_b, p_xnb);

    // 2) QKV = xn @ Wqkv^T + b  (bf16 out)
    {
        dim3 grid(768 / 128, MROWS / 128);
        bgemm_kernel<0, 1><<<grid, 256>>>(p_xnb, p_wqkv, in_proj_b, nullptr,
                                          p_qkvb, MROWS, 3 * Dc, Dc);
    }

    // 3) attention -> o (bf16, reuse g_xnb)
    attn_kernel<<<NWIN * HEADS, 256>>>(p_qkvb, p_xnb);

    // 4) y = x + o @ Wout^T + b  (fp32 out)
    {
        dim3 grid(Dc / 128, MROWS / 128);
        bgemm_kernel<2, 0><<<grid, 256>>>(p_xnb, p_wout, out_b, x, p_y,
                                          MROWS, Dc, Dc);
    }

    // 5) LN2: y -> yn (bf16, into g_qkvb[0:M*256))
    ln_bf_kernel<<<MROWS / 8, 256>>>(p_y, norm2_g, norm2_b, p_qkvb);

    // 6) hmid = gelu(yn @ Wfc1^T + b)  (bf16)
    __nv_bfloat16* p_yn   = p_qkvb;
    __nv_bfloat16* p_hmid = p_qkvb + (size_t)MROWS * Dc;
    {
        dim3 grid(HIDc / 128, MROWS / 128);
        bgemm_kernel<1, 1><<<grid, 256>>>(p_yn, p_wfc1, fc1_b, nullptr,
                                          p_hmid, MROWS, HIDc, Dc);
    }

    // 7) out = y + hmid @ Wfc2^T + b  (fp32)
    {
        dim3 grid(Dc / 128, MROWS / 128);
        bgemm_kernel<2, 0><<<grid, 256>>>(p_hmid, p_wfc2, fc2_b, p_y, out,
                                          MROWS, Dc, HIDc);
    }
}

// round 5
// speedup vs baseline: 2.7079x; 1.9106x over previous
#include <cuda_runtime.h>
#include <cuda_bf16.h>
#include <math.h>
#include <stdint.h>

// Problem constants
#define Bc    8
#define Nc    9856
#define Dc    256
#define HEADS 8
#define HD    32
#define WH    7
#define WW    11
#define L77   77
#define HIDc  512
#define Hc    56
#define Wc    176
#define NH    8
#define NWn   16
#define MROWS (Bc * Nc)       // 78848
#define NWIN  (Bc * NH * NWn) // 1024

// ---------------------------------------------------------------------------
// Scratch (device globals)
// ---------------------------------------------------------------------------
__device__ __nv_bfloat16 g_xnb[(size_t)MROWS * Dc];        // xn, later attn out o
__device__ __nv_bfloat16 g_qkvb[(size_t)MROWS * 3 * Dc];   // qkv, later [yn | hmid]
__device__ float         g_y[(size_t)MROWS * Dc];          // x + attn residual
__device__ __nv_bfloat16 g_wqkv[3 * Dc * Dc];
__device__ __nv_bfloat16 g_wout[Dc * Dc];
__device__ __nv_bfloat16 g_wfc1[HIDc * Dc];
__device__ __nv_bfloat16 g_wfc2[Dc * HIDc];

// ---------------------------------------------------------------------------
// fp32 -> bf16 weight conversion
// ---------------------------------------------------------------------------
__global__ void __launch_bounds__(256) f2bf_kernel(const float* __restrict__ in,
                                                   __nv_bfloat16* __restrict__ out,
                                                   int n)
{
    int i = (blockIdx.x * 256 + threadIdx.x) * 4;
    if (i < n) {
        float4 v = *(const float4*)(in + i);
        union { __nv_bfloat162 h[2]; uint2 u; } pk;
        pk.h[0] = __float22bfloat162_rn(make_float2(v.x, v.y));
        pk.h[1] = __float22bfloat162_rn(make_float2(v.z, v.w));
        *(uint2*)(out + i) = pk.u;
    }
}

// ---------------------------------------------------------------------------
// LayerNorm: one warp per row of 256, bf16 output
// ---------------------------------------------------------------------------
__global__ void __launch_bounds__(256) ln_bf_kernel(const float* __restrict__ x,
                                                    const float* __restrict__ g,
                                                    const float* __restrict__ b,
                                                    __nv_bfloat16* __restrict__ out)
{
    int warp = threadIdx.x >> 5, lane = threadIdx.x & 31;
    size_t row = (size_t)blockIdx.x * 8 + warp;
    const float* xr = x + row * Dc;
    int c = lane * 8;
    float4 v0 = *(const float4*)(xr + c);
    float4 v1 = *(const float4*)(xr + c + 4);
    float sum = v0.x + v0.y + v0.z + v0.w + v1.x + v1.y + v1.z + v1.w;
    float sq  = v0.x*v0.x + v0.y*v0.y + v0.z*v0.z + v0.w*v0.w
              + v1.x*v1.x + v1.y*v1.y + v1.z*v1.z + v1.w*v1.w;
    #pragma unroll
    for (int off = 16; off; off >>= 1) {
        sum += __shfl_xor_sync(0xffffffff, sum, off);
        sq  += __shfl_xor_sync(0xffffffff, sq,  off);
    }
    float mu  = sum * (1.0f / 256.0f);
    float var = sq * (1.0f / 256.0f) - mu * mu;
    float rs  = rsqrtf(var + 1e-5f);
    float4 g0 = *(const float4*)(g + c), g1 = *(const float4*)(g + c + 4);
    float4 b0 = *(const float4*)(b + c), b1 = *(const float4*)(b + c + 4);
    union { __nv_bfloat162 h[4]; uint4 u; } pk;
    pk.h[0] = __float22bfloat162_rn(make_float2((v0.x - mu) * rs * g0.x + b0.x,
                                                (v0.y - mu) * rs * g0.y + b0.y));
    pk.h[1] = __float22bfloat162_rn(make_float2((v0.z - mu) * rs * g0.z + b0.z,
                                                (v0.w - mu) * rs * g0.w + b0.w));
    pk.h[2] = __float22bfloat162_rn(make_float2((v1.x - mu) * rs * g1.x + b1.x,
                                                (v1.y - mu) * rs * g1.y + b1.y));
    pk.h[3] = __float22bfloat162_rn(make_float2((v1.z - mu) * rs * g1.z + b1.z,
                                                (v1.w - mu) * rs * g1.w + b1.w));
    *(uint4*)(out + row * Dc + c) = pk.u;
}

// ---------------------------------------------------------------------------
// MMA helpers
// ---------------------------------------------------------------------------
__device__ __forceinline__ void cp16(uint32_t saddr, const void* g)
{
    asm volatile("cp.async.cg.shared.global [%0], [%1], 16;\n"
                 :: "r"(saddr), "l"(g));
}

__device__ __forceinline__ void ldsm4(uint32_t* r, uint32_t addr)
{
    asm volatile("ldmatrix.sync.aligned.m8n8.x4.shared.b16 {%0,%1,%2,%3}, [%4];"
                 : "=r"(r[0]), "=r"(r[1]), "=r"(r[2]), "=r"(r[3]) : "r"(addr));
}

__device__ __forceinline__ void mma_bf16(float (&c)[4], const uint32_t* a,
                                         uint32_t b0, uint32_t b1)
{
    asm volatile(
        "mma.sync.aligned.m16n8k16.row.col.f32.bf16.bf16.f32 "
        "{%0,%1,%2,%3}, {%4,%5,%6,%7}, {%8,%9}, {%0,%1,%2,%3};"
        : "+f"(c[0]), "+f"(c[1]), "+f"(c[2]), "+f"(c[3])
        : "r"(a[0]), "r"(a[1]), "r"(a[2]), "r"(a[3]), "r"(b0), "r"(b1));
}

__device__ __forceinline__ float gelu_exact(float v)
{
    return 0.5f * v * (1.0f + erff(v * 0.70710678118654752f));
}

__device__ __forceinline__ uint32_t packbf(float a, float b)
{
    union { __nv_bfloat162 h; uint32_t u; } p;
    p.h = __float22bfloat162_rn(make_float2(a, b));
    return p.u;
}

// ---------------------------------------------------------------------------
// bf16 GEMM: C[M,N] = A[M,K] @ B[N,K]^T + bias (+epilogue)
// CTA 128x128, BK=32, 8 warps (2x4), warp tile 64x32, m16n8k16 mma.
// 3-stage cp.async pipeline (dynamic smem), compile-time K (full unroll),
// one __syncthreads per K-tile. Pitch 40 bf16 rows (conflict-free ldmatrix).
// EPI 0: bias; 1: bias+GELU; 2: bias+residual.  OBF: bf16 vs fp32 output.
// ---------------------------------------------------------------------------
#define GSTG 10240u                 // bytes per stage per matrix (128*40*2)
#define GEMM_SMEM (3 * 2 * 10240)   // 61440

template <int EPI, int OBF, int K>
__global__ void __launch_bounds__(256, 2) bgemm_kernel(const __nv_bfloat16* __restrict__ A,
                                                       const __nv_bfloat16* __restrict__ B,
                                                       const float* __restrict__ bias,
                                                       const float* __restrict__ resid,
                                                       void* __restrict__ Cv,
                                                       int M, int N)
{
    extern __shared__ __nv_bfloat16 dyn[];
    __nv_bfloat16* sA = dyn;                 // 3 stages
    __nv_bfloat16* sB = dyn + 3 * 128 * 40;  // 3 stages

    int tid = threadIdx.x, lane = tid & 31, warp = tid >> 5;
    int wm = warp >> 2, wn = warp & 3;
    int m0 = blockIdx.y * 128, n0 = blockIdx.x * 128;

    int srow = tid >> 1, scb = (tid & 1) * 2;
    const __nv_bfloat16* gA = A + (size_t)(m0 + srow) * K + scb * 8;
    const __nv_bfloat16* gB = B + (size_t)(n0 + srow) * K + scb * 8;
    uint32_t swA = (uint32_t)__cvta_generic_to_shared(&sA[srow * 40 + scb * 8]);
    uint32_t swB = (uint32_t)__cvta_generic_to_shared(&sB[srow * 40 + scb * 8]);

    int a_row = lane & 15;
    int a_c   = lane >> 4;
    int b_row = (lane & 7) | (((lane >> 4) & 1) << 3);
    int b_c   = (lane >> 3) & 1;
    uint32_t lA = (uint32_t)__cvta_generic_to_shared(&sA[(wm * 64 + a_row) * 40]) + a_c * 16;
    uint32_t lB = (uint32_t)__cvta_generic_to_shared(&sB[(wn * 32 + b_row) * 40]) + b_c * 16;

    float acc[4][4][4] = {};
    constexpr int KT = K >> 5;

    #pragma unroll
    for (int s = 0; s < 2; s++) {
        cp16(swA + s * GSTG,      gA + s * 32);
        cp16(swA + s * GSTG + 16, gA + s * 32 + 8);
        cp16(swB + s * GSTG,      gB + s * 32);
        cp16(swB + s * GSTG + 16, gB + s * 32 + 8);
        asm volatile("cp.async.commit_group;");
    }

    #pragma unroll
    for (int kt = 0; kt < KT; kt++) {
        asm volatile("cp.async.wait_group 1;");
        __syncthreads();
        const int buf = kt % 3;
        uint32_t aB = lA + buf * GSTG, bB = lB + buf * GSTG;
        #pragma unroll
        for (int kk = 0; kk < 2; kk++) {
            uint32_t a[4][4], b[2][4];
            #pragma unroll
            for (int mt = 0; mt < 4; mt++)
                ldsm4(a[mt], aB + mt * 1280 + kk * 32);
            #pragma unroll
            for (int p = 0; p < 2; p++)
                ldsm4(b[p], bB + p * 1280 + kk * 32);
            #pragma unroll
            for (int mt = 0; mt < 4; mt++) {
                mma_bf16(acc[mt][0], a[mt], b[0][0], b[0][1]);
                mma_bf16(acc[mt][1], a[mt], b[0][2], b[0][3]);
                mma_bf16(acc[mt][2], a[mt], b[1][0], b[1][1]);
                mma_bf16(acc[mt][3], a[mt], b[1][2], b[1][3]);
            }
        }
        if (kt + 2 < KT) {
            const int wbuf = (kt + 2) % 3;
            cp16(swA + wbuf * GSTG,      gA + (kt + 2) * 32);
            cp16(swA + wbuf * GSTG + 16, gA + (kt + 2) * 32 + 8);
            cp16(swB + wbuf * GSTG,      gB + (kt + 2) * 32);
            cp16(swB + wbuf * GSTG + 16, gB + (kt + 2) * 32 + 8);
        }
        asm volatile("cp.async.commit_group;");
    }

    float* Cf = (float*)Cv;
    __nv_bfloat16* Cb = (__nv_bfloat16*)Cv;
    int g = lane >> 2, t = lane & 3;
    #pragma unroll
    for (int mt = 0; mt < 4; mt++) {
        size_t r0 = (size_t)m0 + wm * 64 + mt * 16 + g;
        size_t r1 = r0 + 8;
        #pragma unroll
        for (int nt = 0; nt < 4; nt++) {
            int col = n0 + wn * 32 + nt * 8 + 2 * t;
            float b0 = bias[col], b1 = bias[col + 1];
            float v00 = acc[mt][nt][0] + b0, v01 = acc[mt][nt][1] + b1;
            float v10 = acc[mt][nt][2] + b0, v11 = acc[mt][nt][3] + b1;
            if (EPI == 1) {
                v00 = gelu_exact(v00); v01 = gelu_exact(v01);
                v10 = gelu_exact(v10); v11 = gelu_exact(v11);
            }
            if (EPI == 2) {
                float2 q0 = *(const float2*)&resid[r0 * N + col];
                float2 q1 = *(const float2*)&resid[r1 * N + col];
                v00 += q0.x; v01 += q0.y; v10 += q1.x; v11 += q1.y;
            }
            if (OBF) {
                *(uint32_t*)&Cb[r0 * N + col] = packbf(v00, v01);
                *(uint32_t*)&Cb[r1 * N + col] = packbf(v10, v11);
            } else {
                *(float2*)&Cf[r0 * N + col] = make_float2(v00, v01);
                *(float2*)&Cf[r1 * N + col] = make_float2(v10, v11);
            }
        }
    }
}

// ---------------------------------------------------------------------------
// Windowed attention via bf16 mma. CTA = (window, head), 5 warps x 16 rows,
// L padded to 80. S=Q@K^T (fp32 acc) -> softmax in regs -> P(bf16) @ V.
// ---------------------------------------------------------------------------
__device__ __forceinline__ int rowmap(int wi, int l)
{
    int b   = wi >> 7;
    int rem = wi & 127;
    int hb  = rem >> 4;
    int wb  = rem & 15;
    int r   = l / WW;
    int c   = l - r * WW;
    return b * Nc + (hb * WH + r) * Wc + wb * WW + c;
}

__global__ void __launch_bounds__(160) attn_kernel(const __nv_bfloat16* __restrict__ qkv,
                                                   __nv_bfloat16* __restrict__ o)
{
    __shared__ __nv_bfloat16 sQ[80 * 40];
    __shared__ __nv_bfloat16 sK[80 * 40];
    __shared__ __nv_bfloat16 sVt[32 * 88];

    int bx = blockIdx.x, wi = bx >> 3, h = bx & 7;
    int tid = threadIdx.x, lane = tid & 31, w = tid >> 5;

    // Gather: 20 rows per pass (8 threads x 8B per row), zero-fill pads
    int lrow = tid >> 3, lseg = tid & 7;
    #pragma unroll
    for (int r0 = 0; r0 < 80; r0 += 20) {
        int l = r0 + lrow;
        uint2 qv = make_uint2(0, 0), kv = qv, vv = qv;
        if (l < L77) {
            int grow = rowmap(wi, l);
            const __nv_bfloat16* base = qkv + (size_t)grow * (3 * Dc) + h * HD + lseg * 4;
            qv = *(const uint2*)(base);
            kv = *(const uint2*)(base + Dc);
            vv = *(const uint2*)(base + 2 * Dc);
        }
        *(uint2*)&sQ[l * 40 + lseg * 4] = qv;
        *(uint2*)&sK[l * 40 + lseg * 4] = kv;
        union { uint2 u; __nv_bfloat16 h[4]; } vu; vu.u = vv;
        #pragma unroll
        for (int j = 0; j < 4; j++)
            sVt[(lseg * 4 + j) * 88 + l] = vu.h[j];
    }
    __syncthreads();

    int a_row = lane & 15;
    int a_c   = lane >> 4;
    int b_row = (lane & 7) | (((lane >> 4) & 1) << 3);
    int b_c   = (lane >> 3) & 1;
    int g = lane >> 2, t = lane & 3;

    uint32_t aQ = (uint32_t)__cvta_generic_to_shared(&sQ[(w * 16 + a_row) * 40]) + a_c * 16;
    uint32_t bK = (uint32_t)__cvta_generic_to_shared(&sK[b_row * 40]) + b_c * 16;
    uint32_t bV = (uint32_t)__cvta_generic_to_shared(&sVt[b_row * 88]) + b_c * 16;

    // S = Q @ K^T : 10 n8 tiles, fp32 acc
    float s[10][4] = {};
    uint32_t aq[2][4];
    ldsm4(aq[0], aQ);
    ldsm4(aq[1], aQ + 32);
    #pragma unroll
    for (int kk = 0; kk < 2; kk++) {
        #pragma unroll
        for (int p = 0; p < 5; p++) {
            uint32_t b[4];
            ldsm4(b, bK + p * 1280 + kk * 32);
            mma_bf16(s[2 * p],     aq[kk], b[0], b[1]);
            mma_bf16(s[2 * p + 1], aq[kk], b[2], b[3]);
        }
    }

    // Mask key-padding cols 77..79 (tile 9 covers cols 72..79)
    if (72 + 2 * t >= L77) { s[9][0] = -1e30f; s[9][2] = -1e30f; }
    if (73 + 2 * t >= L77) { s[9][1] = -1e30f; s[9][3] = -1e30f; }

    // Row softmax (rows g and g+8), scale folded into exp arg
    const float scale = 0.17677669529663687f;  // 1/sqrt(32)
    float mx0 = -1e30f, mx1 = -1e30f;
    #pragma unroll
    for (int nt = 0; nt < 10; nt++) {
        mx0 = fmaxf(mx0, fmaxf(s[nt][0], s[nt][1]));
        mx1 = fmaxf(mx1, fmaxf(s[nt][2], s[nt][3]));
    }
    mx0 = fmaxf(mx0, __shfl_xor_sync(0xffffffff, mx0, 1));
    mx0 = fmaxf(mx0, __shfl_xor_sync(0xffffffff, mx0, 2));
    mx1 = fmaxf(mx1, __shfl_xor_sync(0xffffffff, mx1, 1));
    mx1 = fmaxf(mx1, __shfl_xor_sync(0xffffffff, mx1, 2));
    float ms0 = mx0 * scale, ms1 = mx1 * scale;

    float e[10][4];
    float sum0 = 0.f, sum1 = 0.f;
    #pragma unroll
    for (int nt = 0; nt < 10; nt++) {
        e[nt][0] = __expf(fmaf(s[nt][0], scale, -ms0));
        e[nt][1] = __expf(fmaf(s[nt][1], scale, -ms0));
        e[nt][2] = __expf(fmaf(s[nt][2], scale, -ms1));
        e[nt][3] = __expf(fmaf(s[nt][3], scale, -ms1));
        sum0 += e[nt][0] + e[nt][1];
        sum1 += e[nt][2] + e[nt][3];
    }
    sum0 += __shfl_xor_sync(0xffffffff, sum0, 1);
    sum0 += __shfl_xor_sync(0xffffffff, sum0, 2);
    sum1 += __shfl_xor_sync(0xffffffff, sum1, 1);
    sum1 += __shfl_xor_sync(0xffffffff, sum1, 2);
    float inv0 = 1.0f / sum0, inv1 = 1.0f / sum1;

    // Pack unnormalized P into bf16 A-fragments (5 k16 steps)
    uint32_t pa[5][4];
    #pragma unroll
    for (int kf = 0; kf < 5; kf++) {
        pa[kf][0] = packbf(e[2 * kf][0],     e[2 * kf][1]);
        pa[kf][1] = packbf(e[2 * kf][2],     e[2 * kf][3]);
        pa[kf][2] = packbf(e[2 * kf + 1][0], e[2 * kf + 1][1]);
        pa[kf][3] = packbf(e[2 * kf + 1][2], e[2 * kf + 1][3]);
    }

    // O = P @ V : 4 n8 tiles (hd=32)
    float oa[4][4] = {};
    #pragma unroll
    for (int kf = 0; kf < 5; kf++) {
        #pragma unroll
        for (int vt = 0; vt < 2; vt++) {
            uint32_t b[4];
            ldsm4(b, bV + vt * 2816 + kf * 32);
            mma_bf16(oa[2 * vt],     pa[kf], b[0], b[1]);
            mma_bf16(oa[2 * vt + 1], pa[kf], b[2], b[3]);
        }
    }

    // Epilogue: normalize, scatter rows < 77
    int r0 = w * 16 + g, r1 = r0 + 8;
    if (r0 < L77) {
        size_t grow = (size_t)rowmap(wi, r0);
        #pragma unroll
        for (int nt = 0; nt < 4; nt++)
            *(uint32_t*)&o[grow * Dc + h * HD + nt * 8 + 2 * t] =
                packbf(oa[nt][0] * inv0, oa[nt][1] * inv0);
    }
    if (r1 < L77) {
        size_t grow = (size_t)rowmap(wi, r1);
        #pragma unroll
        for (int nt = 0; nt < 4; nt++)
            *(uint32_t*)&o[grow * Dc + h * HD + nt * 8 + 2 * t] =
                packbf(oa[nt][2] * inv1, oa[nt][3] * inv1);
    }
}

// ---------------------------------------------------------------------------
// Launch
// ---------------------------------------------------------------------------
extern "C" void kernel_launch(void* const* d_in, const int* in_sizes, int n_in,
                              void* d_out, int out_size)
{
    const float* x         = (const float*)d_in[0];
    const float* norm1_g   = (const float*)d_in[1];
    const float* norm1_b   = (const float*)d_in[2];
    const float* in_proj_w = (const float*)d_in[3];
    const float* in_proj_b = (const float*)d_in[4];
    const float* out_w     = (const float*)d_in[5];
    const float* out_b     = (const float*)d_in[6];
    const float* norm2_g   = (const float*)d_in[7];
    const float* norm2_b   = (const float*)d_in[8];
    const float* fc1_w     = (const float*)d_in[9];
    const float* fc1_b     = (const float*)d_in[10];
    const float* fc2_w     = (const float*)d_in[11];
    const float* fc2_b     = (const float*)d_in[12];
    float* out = (float*)d_out;

    __nv_bfloat16 *p_xnb, *p_qkvb, *p_wqkv, *p_wout, *p_wfc1, *p_wfc2;
    float* p_y;
    cudaGetSymbolAddress((void**)&p_xnb,  g_xnb);
    cudaGetSymbolAddress((void**)&p_qkvb, g_qkvb);
    cudaGetSymbolAddress((void**)&p_y,    g_y);
    cudaGetSymbolAddress((void**)&p_wqkv, g_wqkv);
    cudaGetSymbolAddress((void**)&p_wout, g_wout);
    cudaGetSymbolAddress((void**)&p_wfc1, g_wfc1);
    cudaGetSymbolAddress((void**)&p_wfc2, g_wfc2);

    cudaFuncSetAttribute(bgemm_kernel<0, 1, 256>,
                         cudaFuncAttributeMaxDynamicSharedMemorySize, GEMM_SMEM);
    cudaFuncSetAttribute(bgemm_kernel<2, 0, 256>,
                         cudaFuncAttributeMaxDynamicSharedMemorySize, GEMM_SMEM);
    cudaFuncSetAttribute(bgemm_kernel<1, 1, 256>,
                         cudaFuncAttributeMaxDynamicSharedMemorySize, GEMM_SMEM);
    cudaFuncSetAttribute(bgemm_kernel<2, 0, 512>,
                         cudaFuncAttributeMaxDynamicSharedMemorySize, GEMM_SMEM);

    // 0) weights fp32 -> bf16
    f2bf_kernel<<<(3 * Dc * Dc) / 1024, 256>>>(in_proj_w, p_wqkv, 3 * Dc * Dc);
    f2bf_kernel<<<(Dc * Dc) / 1024, 256>>>(out_w, p_wout, Dc * Dc);
    f2bf_kernel<<<(HIDc * Dc) / 1024, 256>>>(fc1_w, p_wfc1, HIDc * Dc);
    f2bf_kernel<<<(Dc * HIDc) / 1024, 256>>>(fc2_w, p_wfc2, Dc * HIDc);

    // 1) LN1: x -> xn (bf16)
    ln_bf_kernel<<<MROWS / 8, 256>>>(x, norm1_g, norm1_b, p_xnb);

    // 2) QKV = xn @ Wqkv^T + b  (bf16)
    {
        dim3 grid(768 / 128, MROWS / 128);
        bgemm_kernel<0, 1, 256><<<grid, 256, GEMM_SMEM>>>(p_xnb, p_wqkv, in_proj_b,
                                                          nullptr, p_qkvb, MROWS, 3 * Dc);
    }

    // 3) attention -> o (bf16, reuse g_xnb)
    attn_kernel<<<NWIN * HEADS, 160>>>(p_qkvb, p_xnb);

    // 4) y = x + o @ Wout^T + b  (fp32)
    {
        dim3 grid(Dc / 128, MROWS / 128);
        bgemm_kernel<2, 0, 256><<<grid, 256, GEMM_SMEM>>>(p_xnb, p_wout, out_b,
                                                          x, p_y, MROWS, Dc);
    }

    // 5) LN2: y -> yn (bf16)
    ln_bf_kernel<<<MROWS / 8, 256>>>(p_y, norm2_g, norm2_b, p_qkvb);

    // 6) hmid = gelu(yn @ Wfc1^T + b)  (bf16)
    __nv_bfloat16* p_yn   = p_qkvb;
    __nv_bfloat16* p_hmid = p_qkvb + (size_t)MROWS * Dc;
    {
        dim3 grid(HIDc / 128, MROWS / 128);
        bgemm_kernel<1, 1, 256><<<grid, 256, GEMM_SMEM>>>(p_yn, p_wfc1, fc1_b,
                                                          nullptr, p_hmid, MROWS, HIDc);
    }

    // 7) out = y + hmid @ Wfc2^T + b  (fp32)
    {
        dim3 grid(Dc / 128, MROWS / 128);
        bgemm_kernel<2, 0, 512><<<grid, 256, GEMM_SMEM>>>(p_hmid, p_wfc2, fc2_b,
                                                          p_y, out, MROWS, Dc);
    }
}

// round 6
// speedup vs baseline: 2.7081x; 1.0001x over previous
#include <cuda_runtime.h>
#include <cuda_bf16.h>
#include <math.h>
#include <stdint.h>

// Problem constants
#define Bc    8
#define Nc    9856
#define Dc    256
#define HEADS 8
#define HD    32
#define WH    7
#define WW    11
#define L77   77
#define HIDc  512
#define Hc    56
#define Wc    176
#define NH    8
#define NWn   16
#define MROWS (Bc * Nc)       // 78848
#define NWIN  (Bc * NH * NWn) // 1024

// ---------------------------------------------------------------------------
// Scratch (device globals)
// ---------------------------------------------------------------------------
__device__ __nv_bfloat16 g_xnb[(size_t)MROWS * Dc];        // xn, later attn out o
__device__ __nv_bfloat16 g_qkvb[(size_t)MROWS * 3 * Dc];   // qkv, later [yn | hmid]
__device__ float         g_y[(size_t)MROWS * Dc];          // x + attn residual
__device__ __nv_bfloat16 g_wqkv[3 * Dc * Dc];
__device__ __nv_bfloat16 g_wout[Dc * Dc];
__device__ __nv_bfloat16 g_wfc1[HIDc * Dc];
__device__ __nv_bfloat16 g_wfc2[Dc * HIDc];

// ---------------------------------------------------------------------------
// fp32 -> bf16 weight conversion, all four weights in one launch
// units (float4): wqkv 49152 | wout 16384 | wfc1 32768 | wfc2 32768 = 131072
// ---------------------------------------------------------------------------
__global__ void __launch_bounds__(256) f2bf_all_kernel(const float* __restrict__ w0,
                                                       const float* __restrict__ w1,
                                                       const float* __restrict__ w2,
                                                       const float* __restrict__ w3,
                                                       __nv_bfloat16* __restrict__ o0,
                                                       __nv_bfloat16* __restrict__ o1,
                                                       __nv_bfloat16* __restrict__ o2,
                                                       __nv_bfloat16* __restrict__ o3)
{
    int u = blockIdx.x * 256 + threadIdx.x;
    const float* src;
    __nv_bfloat16* dst;
    int base;
    if (u < 49152)      { src = w0; dst = o0; base = 0; }
    else if (u < 65536) { src = w1; dst = o1; base = 49152; }
    else if (u < 98304) { src = w2; dst = o2; base = 65536; }
    else                { src = w3; dst = o3; base = 98304; }
    int i = (u - base) * 4;
    float4 v = *(const float4*)(src + i);
    union { __nv_bfloat162 h[2]; uint2 u2; } pk;
    pk.h[0] = __float22bfloat162_rn(make_float2(v.x, v.y));
    pk.h[1] = __float22bfloat162_rn(make_float2(v.z, v.w));
    *(uint2*)(dst + i) = pk.u2;
}

// ---------------------------------------------------------------------------
// LayerNorm: one warp per row of 256, bf16 output (used for LN1 only)
// ---------------------------------------------------------------------------
__global__ void __launch_bounds__(256) ln_bf_kernel(const float* __restrict__ x,
                                                    const float* __restrict__ g,
                                                    const float* __restrict__ b,
                                                    __nv_bfloat16* __restrict__ out)
{
    int warp = threadIdx.x >> 5, lane = threadIdx.x & 31;
    size_t row = (size_t)blockIdx.x * 8 + warp;
    const float* xr = x + row * Dc;
    int c = lane * 8;
    float4 v0 = *(const float4*)(xr + c);
    float4 v1 = *(const float4*)(xr + c + 4);
    float sum = v0.x + v0.y + v0.z + v0.w + v1.x + v1.y + v1.z + v1.w;
    float sq  = v0.x*v0.x + v0.y*v0.y + v0.z*v0.z + v0.w*v0.w
              + v1.x*v1.x + v1.y*v1.y + v1.z*v1.z + v1.w*v1.w;
    #pragma unroll
    for (int off = 16; off; off >>= 1) {
        sum += __shfl_xor_sync(0xffffffff, sum, off);
        sq  += __shfl_xor_sync(0xffffffff, sq,  off);
    }
    float mu  = sum * (1.0f / 256.0f);
    float var = sq * (1.0f / 256.0f) - mu * mu;
    float rs  = rsqrtf(var + 1e-5f);
    float4 g0 = *(const float4*)(g + c), g1 = *(const float4*)(g + c + 4);
    float4 b0 = *(const float4*)(b + c), b1 = *(const float4*)(b + c + 4);
    union { __nv_bfloat162 h[4]; uint4 u; } pk;
    pk.h[0] = __float22bfloat162_rn(make_float2((v0.x - mu) * rs * g0.x + b0.x,
                                                (v0.y - mu) * rs * g0.y + b0.y));
    pk.h[1] = __float22bfloat162_rn(make_float2((v0.z - mu) * rs * g0.z + b0.z,
                                                (v0.w - mu) * rs * g0.w + b0.w));
    pk.h[2] = __float22bfloat162_rn(make_float2((v1.x - mu) * rs * g1.x + b1.x,
                                                (v1.y - mu) * rs * g1.y + b1.y));
    pk.h[3] = __float22bfloat162_rn(make_float2((v1.z - mu) * rs * g1.z + b1.z,
                                                (v1.w - mu) * rs * g1.w + b1.w));
    *(uint4*)(out + row * Dc + c) = pk.u;
}

// ---------------------------------------------------------------------------
// MMA helpers
// ---------------------------------------------------------------------------
__device__ __forceinline__ void cp16(uint32_t saddr, const void* g)
{
    asm volatile("cp.async.cg.shared.global [%0], [%1], 16;\n"
                 :: "r"(saddr), "l"(g));
}

__device__ __forceinline__ void ldsm4(uint32_t* r, uint32_t addr)
{
    asm volatile("ldmatrix.sync.aligned.m8n8.x4.shared.b16 {%0,%1,%2,%3}, [%4];"
                 : "=r"(r[0]), "=r"(r[1]), "=r"(r[2]), "=r"(r[3]) : "r"(addr));
}

__device__ __forceinline__ void mma_bf16(float (&c)[4], const uint32_t* a,
                                         uint32_t b0, uint32_t b1)
{
    asm volatile(
        "mma.sync.aligned.m16n8k16.row.col.f32.bf16.bf16.f32 "
        "{%0,%1,%2,%3}, {%4,%5,%6,%7}, {%8,%9}, {%0,%1,%2,%3};"
        : "+f"(c[0]), "+f"(c[1]), "+f"(c[2]), "+f"(c[3])
        : "r"(a[0]), "r"(a[1]), "r"(a[2]), "r"(a[3]), "r"(b0), "r"(b1));
}

__device__ __forceinline__ float gelu_exact(float v)
{
    return 0.5f * v * (1.0f + erff(v * 0.70710678118654752f));
}

__device__ __forceinline__ uint32_t packbf(float a, float b)
{
    union { __nv_bfloat162 h; uint32_t u; } p;
    p.h = __float22bfloat162_rn(make_float2(a, b));
    return p.u;
}

// ---------------------------------------------------------------------------
// bf16 GEMM (128x128 tile): C = A @ B^T + bias (+epilogue)
// EPI 0: bias; 1: bias+GELU; 2: bias+residual.  OBF: bf16 vs fp32 output.
// ---------------------------------------------------------------------------
#define GSTG 10240u
#define GEMM_SMEM (3 * 2 * 10240)

template <int EPI, int OBF, int K>
__global__ void __launch_bounds__(256, 2) bgemm_kernel(const __nv_bfloat16* __restrict__ A,
                                                       const __nv_bfloat16* __restrict__ B,
                                                       const float* __restrict__ bias,
                                                       const float* __restrict__ resid,
                                                       void* __restrict__ Cv,
                                                       int M, int N)
{
    extern __shared__ __nv_bfloat16 dyn[];
    __nv_bfloat16* sA = dyn;
    __nv_bfloat16* sB = dyn + 3 * 128 * 40;

    int tid = threadIdx.x, lane = tid & 31, warp = tid >> 5;
    int wm = warp >> 2, wn = warp & 3;
    int m0 = blockIdx.y * 128, n0 = blockIdx.x * 128;

    int srow = tid >> 1, scb = (tid & 1) * 2;
    const __nv_bfloat16* gA = A + (size_t)(m0 + srow) * K + scb * 8;
    const __nv_bfloat16* gB = B + (size_t)(n0 + srow) * K + scb * 8;
    uint32_t swA = (uint32_t)__cvta_generic_to_shared(&sA[srow * 40 + scb * 8]);
    uint32_t swB = (uint32_t)__cvta_generic_to_shared(&sB[srow * 40 + scb * 8]);

    int a_row = lane & 15;
    int a_c   = lane >> 4;
    int b_row = (lane & 7) | (((lane >> 4) & 1) << 3);
    int b_c   = (lane >> 3) & 1;
    uint32_t lA = (uint32_t)__cvta_generic_to_shared(&sA[(wm * 64 + a_row) * 40]) + a_c * 16;
    uint32_t lB = (uint32_t)__cvta_generic_to_shared(&sB[(wn * 32 + b_row) * 40]) + b_c * 16;

    float acc[4][4][4] = {};
    constexpr int KT = K >> 5;

    #pragma unroll
    for (int s = 0; s < 2; s++) {
        cp16(swA + s * GSTG,      gA + s * 32);
        cp16(swA + s * GSTG + 16, gA + s * 32 + 8);
        cp16(swB + s * GSTG,      gB + s * 32);
        cp16(swB + s * GSTG + 16, gB + s * 32 + 8);
        asm volatile("cp.async.commit_group;");
    }

    #pragma unroll
    for (int kt = 0; kt < KT; kt++) {
        asm volatile("cp.async.wait_group 1;");
        __syncthreads();
        const int buf = kt % 3;
        uint32_t aB = lA + buf * GSTG, bB = lB + buf * GSTG;
        #pragma unroll
        for (int kk = 0; kk < 2; kk++) {
            uint32_t a[4][4], b[2][4];
            #pragma unroll
            for (int mt = 0; mt < 4; mt++)
                ldsm4(a[mt], aB + mt * 1280 + kk * 32);
            #pragma unroll
            for (int p = 0; p < 2; p++)
                ldsm4(b[p], bB + p * 1280 + kk * 32);
            #pragma unroll
            for (int mt = 0; mt < 4; mt++) {
                mma_bf16(acc[mt][0], a[mt], b[0][0], b[0][1]);
                mma_bf16(acc[mt][1], a[mt], b[0][2], b[0][3]);
                mma_bf16(acc[mt][2], a[mt], b[1][0], b[1][1]);
                mma_bf16(acc[mt][3], a[mt], b[1][2], b[1][3]);
            }
        }
        if (kt + 2 < KT) {
            const int wbuf = (kt + 2) % 3;
            cp16(swA + wbuf * GSTG,      gA + (kt + 2) * 32);
            cp16(swA + wbuf * GSTG + 16, gA + (kt + 2) * 32 + 8);
            cp16(swB + wbuf * GSTG,      gB + (kt + 2) * 32);
            cp16(swB + wbuf * GSTG + 16, gB + (kt + 2) * 32 + 8);
        }
        asm volatile("cp.async.commit_group;");
    }

    float* Cf = (float*)Cv;
    __nv_bfloat16* Cb = (__nv_bfloat16*)Cv;
    int g = lane >> 2, t = lane & 3;
    #pragma unroll
    for (int mt = 0; mt < 4; mt++) {
        size_t r0 = (size_t)m0 + wm * 64 + mt * 16 + g;
        size_t r1 = r0 + 8;
        #pragma unroll
        for (int nt = 0; nt < 4; nt++) {
            int col = n0 + wn * 32 + nt * 8 + 2 * t;
            float b0 = bias[col], b1 = bias[col + 1];
            float v00 = acc[mt][nt][0] + b0, v01 = acc[mt][nt][1] + b1;
            float v10 = acc[mt][nt][2] + b0, v11 = acc[mt][nt][3] + b1;
            if (EPI == 1) {
                v00 = gelu_exact(v00); v01 = gelu_exact(v01);
                v10 = gelu_exact(v10); v11 = gelu_exact(v11);
            }
            if (EPI == 2) {
                float2 q0 = *(const float2*)&resid[r0 * N + col];
                float2 q1 = *(const float2*)&resid[r1 * N + col];
                v00 += q0.x; v01 += q0.y; v10 += q1.x; v11 += q1.y;
            }
            if (OBF) {
                *(uint32_t*)&Cb[r0 * N + col] = packbf(v00, v01);
                *(uint32_t*)&Cb[r1 * N + col] = packbf(v10, v11);
            } else {
                *(float2*)&Cf[r0 * N + col] = make_float2(v00, v01);
                *(float2*)&Cf[r1 * N + col] = make_float2(v10, v11);
            }
        }
    }
}

// ---------------------------------------------------------------------------
// Out-projection + residual + fused LayerNorm2.
// CTA tile 128x256 (full N), 8 warps (2x4), warp tile 64x64, K=256.
// y = x + o @ Wout^T + bias (fp32 out); yn = LN(y) (bf16 out).
// ---------------------------------------------------------------------------
#define OSTG_A 10240u              // 128*40*2
#define OSTG_B 20480u              // 256*40*2
#define OGEMM_SMEM (3 * (10240 + 20480))   // 92160

__global__ void __launch_bounds__(256, 1) ogemm_ln_kernel(const __nv_bfloat16* __restrict__ A,
                                                          const __nv_bfloat16* __restrict__ B,
                                                          const float* __restrict__ bias,
                                                          const float* __restrict__ resid,
                                                          const float* __restrict__ g2,
                                                          const float* __restrict__ b2,
                                                          float* __restrict__ Y,
                                                          __nv_bfloat16* __restrict__ YN)
{
    extern __shared__ __nv_bfloat16 dyn[];
    __nv_bfloat16* sA = dyn;                  // 3 stages of 128x40
    __nv_bfloat16* sB = dyn + 3 * 128 * 40;   // 3 stages of 256x40
    __shared__ float2 s_part[4][128];
    __shared__ float2 s_murs[128];

    const int K = 256;
    int tid = threadIdx.x, lane = tid & 31, warp = tid >> 5;
    int wm = warp >> 2, wn = warp & 3;
    int m0 = blockIdx.x * 128;

    int srowA = tid >> 1, scbA = (tid & 1) * 2;
    const __nv_bfloat16* gA = A + (size_t)(m0 + srowA) * K + scbA * 8;
    const __nv_bfloat16* gB = B + (size_t)tid * K;
    uint32_t swA = (uint32_t)__cvta_generic_to_shared(&sA[srowA * 40 + scbA * 8]);
    uint32_t swB = (uint32_t)__cvta_generic_to_shared(&sB[tid * 40]);

    int a_row = lane & 15;
    int a_c   = lane >> 4;
    int b_row = (lane & 7) | (((lane >> 4) & 1) << 3);
    int b_c   = (lane >> 3) & 1;
    int g = lane >> 2, t = lane & 3;
    uint32_t lA = (uint32_t)__cvta_generic_to_shared(&sA[(wm * 64 + a_row) * 40]) + a_c * 16;
    uint32_t lB = (uint32_t)__cvta_generic_to_shared(&sB[(wn * 64 + b_row) * 40]) + b_c * 16;

    float acc[4][8][4] = {};

    #pragma unroll
    for (int s = 0; s < 2; s++) {
        cp16(swA + s * OSTG_A,      gA + s * 32);
        cp16(swA + s * OSTG_A + 16, gA + s * 32 + 8);
        #pragma unroll
        for (int c = 0; c < 4; c++)
            cp16(swB + s * OSTG_B + c * 16, gB + s * 32 + c * 8);
        asm volatile("cp.async.commit_group;");
    }

    #pragma unroll
    for (int kt = 0; kt < 8; kt++) {
        asm volatile("cp.async.wait_group 1;");
        __syncthreads();
        const int buf = kt % 3;
        uint32_t aB = lA + buf * OSTG_A, bB = lB + buf * OSTG_B;
        #pragma unroll
        for (int kk = 0; kk < 2; kk++) {
            uint32_t a[4][4], b[4][4];
            #pragma unroll
            for (int mt = 0; mt < 4; mt++)
                ldsm4(a[mt], aB + mt * 1280 + kk * 32);
            #pragma unroll
            for (int p = 0; p < 4; p++)
                ldsm4(b[p], bB + p * 1280 + kk * 32);
            #pragma unroll
            for (int mt = 0; mt < 4; mt++)
                #pragma unroll
                for (int p = 0; p < 4; p++) {
                    mma_bf16(acc[mt][2 * p],     a[mt], b[p][0], b[p][1]);
                    mma_bf16(acc[mt][2 * p + 1], a[mt], b[p][2], b[p][3]);
                }
        }
        if (kt + 2 < 8) {
            const int wbuf = (kt + 2) % 3;
            cp16(swA + wbuf * OSTG_A,      gA + (kt + 2) * 32);
            cp16(swA + wbuf * OSTG_A + 16, gA + (kt + 2) * 32 + 8);
            #pragma unroll
            for (int c = 0; c < 4; c++)
                cp16(swB + wbuf * OSTG_B + c * 16, gB + (kt + 2) * 32 + c * 8);
        }
        asm volatile("cp.async.commit_group;");
    }

    // y = acc + bias + resid; write y; accumulate row stats in acc
    float rs_s[4][2] = {};   // [mt][half] partial sums
    float rs_q[4][2] = {};
    #pragma unroll
    for (int mt = 0; mt < 4; mt++) {
        size_t r0 = (size_t)m0 + wm * 64 + mt * 16 + g;
        size_t r1 = r0 + 8;
        #pragma unroll
        for (int nt = 0; nt < 8; nt++) {
            int col = wn * 64 + nt * 8 + 2 * t;
            float bb0 = bias[col], bb1 = bias[col + 1];
            float2 q0 = *(const float2*)&resid[r0 * Dc + col];
            float2 q1 = *(const float2*)&resid[r1 * Dc + col];
            float v00 = acc[mt][nt][0] + bb0 + q0.x;
            float v01 = acc[mt][nt][1] + bb1 + q0.y;
            float v10 = acc[mt][nt][2] + bb0 + q1.x;
            float v11 = acc[mt][nt][3] + bb1 + q1.y;
            acc[mt][nt][0] = v00; acc[mt][nt][1] = v01;
            acc[mt][nt][2] = v10; acc[mt][nt][3] = v11;
            *(float2*)&Y[r0 * Dc + col] = make_float2(v00, v01);
            *(float2*)&Y[r1 * Dc + col] = make_float2(v10, v11);
            rs_s[mt][0] += v00 + v01;  rs_q[mt][0] += v00 * v00 + v01 * v01;
            rs_s[mt][1] += v10 + v11;  rs_q[mt][1] += v10 * v10 + v11 * v11;
        }
    }
    // reduce across the 4 t-lanes (64 cols per warp)
    #pragma unroll
    for (int mt = 0; mt < 4; mt++) {
        #pragma unroll
        for (int hf = 0; hf < 2; hf++) {
            float s = rs_s[mt][hf], q = rs_q[mt][hf];
            s += __shfl_xor_sync(0xffffffff, s, 1);
            q += __shfl_xor_sync(0xffffffff, q, 1);
            s += __shfl_xor_sync(0xffffffff, s, 2);
            q += __shfl_xor_sync(0xffffffff, q, 2);
            if (t == 0)
                s_part[wn][wm * 64 + mt * 16 + hf * 8 + g] = make_float2(s, q);
        }
    }
    __syncthreads();
    if (tid < 128) {
        float s = 0.f, q = 0.f;
        #pragma unroll
        for (int p = 0; p < 4; p++) {
            float2 v = s_part[p][tid];
            s += v.x; q += v.y;
        }
        float mu  = s * (1.0f / 256.0f);
        float var = q * (1.0f / 256.0f) - mu * mu;
        s_murs[tid] = make_float2(mu, rsqrtf(var + 1e-5f));
    }
    __syncthreads();

    #pragma unroll
    for (int mt = 0; mt < 4; mt++) {
        int lr0 = wm * 64 + mt * 16 + g;
        float2 m0r = s_murs[lr0];
        float2 m1r = s_murs[lr0 + 8];
        size_t r0 = (size_t)m0 + lr0;
        size_t r1 = r0 + 8;
        #pragma unroll
        for (int nt = 0; nt < 8; nt++) {
            int col = wn * 64 + nt * 8 + 2 * t;
            float2 gg = *(const float2*)&g2[col];
            float2 bb = *(const float2*)&b2[col];
            float y00 = (acc[mt][nt][0] - m0r.x) * m0r.y * gg.x + bb.x;
            float y01 = (acc[mt][nt][1] - m0r.x) * m0r.y * gg.y + bb.y;
            float y10 = (acc[mt][nt][2] - m1r.x) * m1r.y * gg.x + bb.x;
            float y11 = (acc[mt][nt][3] - m1r.x) * m1r.y * gg.y + bb.y;
            *(uint32_t*)&YN[r0 * Dc + col] = packbf(y00, y01);
            *(uint32_t*)&YN[r1 * Dc + col] = packbf(y10, y11);
        }
    }
}

// ---------------------------------------------------------------------------
// Windowed attention via bf16 mma (unchanged from R5)
// ---------------------------------------------------------------------------
__device__ __forceinline__ int rowmap(int wi, int l)
{
    int b   = wi >> 7;
    int rem = wi & 127;
    int hb  = rem >> 4;
    int wb  = rem & 15;
    int r   = l / WW;
    int c   = l - r * WW;
    return b * Nc + (hb * WH + r) * Wc + wb * WW + c;
}

__global__ void __launch_bounds__(160) attn_kernel(const __nv_bfloat16* __restrict__ qkv,
                                                   __nv_bfloat16* __restrict__ o)
{
    __shared__ __nv_bfloat16 sQ[80 * 40];
    __shared__ __nv_bfloat16 sK[80 * 40];
    __shared__ __nv_bfloat16 sVt[32 * 88];

    int bx = blockIdx.x, wi = bx >> 3, h = bx & 7;
    int tid = threadIdx.x, lane = tid & 31, w = tid >> 5;

    int lrow = tid >> 3, lseg = tid & 7;
    #pragma unroll
    for (int r0 = 0; r0 < 80; r0 += 20) {
        int l = r0 + lrow;
        uint2 qv = make_uint2(0, 0), kv = qv, vv = qv;
        if (l < L77) {
            int grow = rowmap(wi, l);
            const __nv_bfloat16* base = qkv + (size_t)grow * (3 * Dc) + h * HD + lseg * 4;
            qv = *(const uint2*)(base);
            kv = *(const uint2*)(base + Dc);
            vv = *(const uint2*)(base + 2 * Dc);
        }
        *(uint2*)&sQ[l * 40 + lseg * 4] = qv;
        *(uint2*)&sK[l * 40 + lseg * 4] = kv;
        union { uint2 u; __nv_bfloat16 h[4]; } vu; vu.u = vv;
        #pragma unroll
        for (int j = 0; j < 4; j++)
            sVt[(lseg * 4 + j) * 88 + l] = vu.h[j];
    }
    __syncthreads();

    int a_row = lane & 15;
    int a_c   = lane >> 4;
    int b_row = (lane & 7) | (((lane >> 4) & 1) << 3);
    int b_c   = (lane >> 3) & 1;
    int g = lane >> 2, t = lane & 3;

    uint32_t aQ = (uint32_t)__cvta_generic_to_shared(&sQ[(w * 16 + a_row) * 40]) + a_c * 16;
    uint32_t bK = (uint32_t)__cvta_generic_to_shared(&sK[b_row * 40]) + b_c * 16;
    uint32_t bV = (uint32_t)__cvta_generic_to_shared(&sVt[b_row * 88]) + b_c * 16;

    float s[10][4] = {};
    uint32_t aq[2][4];
    ldsm4(aq[0], aQ);
    ldsm4(aq[1], aQ + 32);
    #pragma unroll
    for (int kk = 0; kk < 2; kk++) {
        #pragma unroll
        for (int p = 0; p < 5; p++) {
            uint32_t b[4];
            ldsm4(b, bK + p * 1280 + kk * 32);
            mma_bf16(s[2 * p],     aq[kk], b[0], b[1]);
            mma_bf16(s[2 * p + 1], aq[kk], b[2], b[3]);
        }
    }

    if (72 + 2 * t >= L77) { s[9][0] = -1e30f; s[9][2] = -1e30f; }
    if (73 + 2 * t >= L77) { s[9][1] = -1e30f; s[9][3] = -1e30f; }

    const float scale = 0.17677669529663687f;
    float mx0 = -1e30f, mx1 = -1e30f;
    #pragma unroll
    for (int nt = 0; nt < 10; nt++) {
        mx0 = fmaxf(mx0, fmaxf(s[nt][0], s[nt][1]));
        mx1 = fmaxf(mx1, fmaxf(s[nt][2], s[nt][3]));
    }
    mx0 = fmaxf(mx0, __shfl_xor_sync(0xffffffff, mx0, 1));
    mx0 = fmaxf(mx0, __shfl_xor_sync(0xffffffff, mx0, 2));
    mx1 = fmaxf(mx1, __shfl_xor_sync(0xffffffff, mx1, 1));
    mx1 = fmaxf(mx1, __shfl_xor_sync(0xffffffff, mx1, 2));
    float ms0 = mx0 * scale, ms1 = mx1 * scale;

    float e[10][4];
    float sum0 = 0.f, sum1 = 0.f;
    #pragma unroll
    for (int nt = 0; nt < 10; nt++) {
        e[nt][0] = __expf(fmaf(s[nt][0], scale, -ms0));
        e[nt][1] = __expf(fmaf(s[nt][1], scale, -ms0));
        e[nt][2] = __expf(fmaf(s[nt][2], scale, -ms1));
        e[nt][3] = __expf(fmaf(s[nt][3], scale, -ms1));
        sum0 += e[nt][0] + e[nt][1];
        sum1 += e[nt][2] + e[nt][3];
    }
    sum0 += __shfl_xor_sync(0xffffffff, sum0, 1);
    sum0 += __shfl_xor_sync(0xffffffff, sum0, 2);
    sum1 += __shfl_xor_sync(0xffffffff, sum1, 1);
    sum1 += __shfl_xor_sync(0xffffffff, sum1, 2);
    float inv0 = 1.0f / sum0, inv1 = 1.0f / sum1;

    uint32_t pa[5][4];
    #pragma unroll
    for (int kf = 0; kf < 5; kf++) {
        pa[kf][0] = packbf(e[2 * kf][0],     e[2 * kf][1]);
        pa[kf][1] = packbf(e[2 * kf][2],     e[2 * kf][3]);
        pa[kf][2] = packbf(e[2 * kf + 1][0], e[2 * kf + 1][1]);
        pa[kf][3] = packbf(e[2 * kf + 1][2], e[2 * kf + 1][3]);
    }

    float oa[4][4] = {};
    #pragma unroll
    for (int kf = 0; kf < 5; kf++) {
        #pragma unroll
        for (int vt = 0; vt < 2; vt++) {
            uint32_t b[4];
            ldsm4(b, bV + vt * 2816 + kf * 32);
            mma_bf16(oa[2 * vt],     pa[kf], b[0], b[1]);
            mma_bf16(oa[2 * vt + 1], pa[kf], b[2], b[3]);
        }
    }

    int r0 = w * 16 + g, r1 = r0 + 8;
    if (r0 < L77) {
        size_t grow = (size_t)rowmap(wi, r0);
        #pragma unroll
        for (int nt = 0; nt < 4; nt++)
            *(uint32_t*)&o[grow * Dc + h * HD + nt * 8 + 2 * t] =
                packbf(oa[nt][0] * inv0, oa[nt][1] * inv0);
    }
    if (r1 < L77) {
        size_t grow = (size_t)rowmap(wi, r1);
        #pragma unroll
        for (int nt = 0; nt < 4; nt++)
            *(uint32_t*)&o[grow * Dc + h * HD + nt * 8 + 2 * t] =
                packbf(oa[nt][2] * inv1, oa[nt][3] * inv1);
    }
}

// ---------------------------------------------------------------------------
// Launch
// ---------------------------------------------------------------------------
extern "C" void kernel_launch(void* const* d_in, const int* in_sizes, int n_in,
                              void* d_out, int out_size)
{
    const float* x         = (const float*)d_in[0];
    const float* norm1_g   = (const float*)d_in[1];
    const float* norm1_b   = (const float*)d_in[2];
    const float* in_proj_w = (const float*)d_in[3];
    const float* in_proj_b = (const float*)d_in[4];
    const float* out_w     = (const float*)d_in[5];
    const float* out_b     = (const float*)d_in[6];
    const float* norm2_g   = (const float*)d_in[7];
    const float* norm2_b   = (const float*)d_in[8];
    const float* fc1_w     = (const float*)d_in[9];
    const float* fc1_b     = (const float*)d_in[10];
    const float* fc2_w     = (const float*)d_in[11];
    const float* fc2_b     = (const float*)d_in[12];
    float* out = (float*)d_out;

    __nv_bfloat16 *p_xnb, *p_qkvb, *p_wqkv, *p_wout, *p_wfc1, *p_wfc2;
    float* p_y;
    cudaGetSymbolAddress((void**)&p_xnb,  g_xnb);
    cudaGetSymbolAddress((void**)&p_qkvb, g_qkvb);
    cudaGetSymbolAddress((void**)&p_y,    g_y);
    cudaGetSymbolAddress((void**)&p_wqkv, g_wqkv);
    cudaGetSymbolAddress((void**)&p_wout, g_wout);
    cudaGetSymbolAddress((void**)&p_wfc1, g_wfc1);
    cudaGetSymbolAddress((void**)&p_wfc2, g_wfc2);

    cudaFuncSetAttribute(bgemm_kernel<0, 1, 256>,
                         cudaFuncAttributeMaxDynamicSharedMemorySize, GEMM_SMEM);
    cudaFuncSetAttribute(bgemm_kernel<1, 1, 256>,
                         cudaFuncAttributeMaxDynamicSharedMemorySize, GEMM_SMEM);
    cudaFuncSetAttribute(bgemm_kernel<2, 0, 512>,
                         cudaFuncAttributeMaxDynamicSharedMemorySize, GEMM_SMEM);
    cudaFuncSetAttribute(ogemm_ln_kernel,
                         cudaFuncAttributeMaxDynamicSharedMemorySize, OGEMM_SMEM);

    // 0) weights fp32 -> bf16 (single launch)
    f2bf_all_kernel<<<512, 256>>>(in_proj_w, out_w, fc1_w, fc2_w,
                                  p_wqkv, p_wout, p_wfc1, p_wfc2);

    // 1) LN1: x -> xn (bf16)
    ln_bf_kernel<<<MROWS / 8, 256>>>(x, norm1_g, norm1_b, p_xnb);

    // 2) QKV = xn @ Wqkv^T + b  (bf16)
    {
        dim3 grid(768 / 128, MROWS / 128);
        bgemm_kernel<0, 1, 256><<<grid, 256, GEMM_SMEM>>>(p_xnb, p_wqkv, in_proj_b,
                                                          nullptr, p_qkvb, MROWS, 3 * Dc);
    }

    // 3) attention -> o (bf16, reuse g_xnb)
    attn_kernel<<<NWIN * HEADS, 160>>>(p_qkvb, p_xnb);

    // 4+5) y = x + o @ Wout^T + b (fp32) AND yn = LN2(y) (bf16) fused
    ogemm_ln_kernel<<<MROWS / 128, 256, OGEMM_SMEM>>>(p_xnb, p_wout, out_b, x,
                                                      norm2_g, norm2_b, p_y, p_qkvb);

    // 6) hmid = gelu(yn @ Wfc1^T + b)  (bf16)
    __nv_bfloat16* p_yn   = p_qkvb;
    __nv_bfloat16* p_hmid = p_qkvb + (size_t)MROWS * Dc;
    {
        dim3 grid(HIDc / 128, MROWS / 128);
        bgemm_kernel<1, 1, 256><<<grid, 256, GEMM_SMEM>>>(p_yn, p_wfc1, fc1_b,
                                                          nullptr, p_hmid, MROWS, HIDc);
    }

    // 7) out = y + hmid @ Wfc2^T + b  (fp32)
    {
        dim3 grid(Dc / 128, MROWS / 128);
        bgemm_kernel<2, 0, 512><<<grid, 256, GEMM_SMEM>>>(p_hmid, p_wfc2, fc2_b,
                                                          p_y, out, MROWS, Dc);
    }
}

// round 8
// speedup vs baseline: 3.2581x; 1.2031x over previous
#include <cuda_runtime.h>
#include <cuda_bf16.h>
#include <math.h>
#include <stdint.h>

// Problem constants
#define Bc    8
#define Nc    9856
#define Dc    256
#define HEADS 8
#define HD    32
#define WH    7
#define WW    11
#define L77   77
#define HIDc  512
#define Hc    56
#define Wc    176
#define NH    8
#define NWn   16
#define MROWS (Bc * Nc)       // 78848
#define NWIN  (Bc * NH * NWn) // 1024

// Tiled image layout: for matrix [R][K], tile (rb=r/128, kt=k/64) is an 8192-elem
// (16 KB) block at ((rb*(K/64))+kt)*8192. Inside: row r%128 occupies 64 elems
// (128 B); 16B chunk c (=within-tile k/8) stored at position (c ^ (row&7)).
// This is exactly the SW128 smem image, so GEMMs bulk-copy tiles verbatim.

// ---------------------------------------------------------------------------
// Scratch (device globals)
// ---------------------------------------------------------------------------
__device__ __nv_bfloat16 g_xnb[(size_t)MROWS * Dc];        // xn image; later o image
__device__ __nv_bfloat16 g_qkvb[(size_t)MROWS * 3 * Dc];   // qkv row-major; later [yn img | hmid img]
__device__ float         g_y[(size_t)MROWS * Dc];          // x + attn residual (row-major fp32)
__device__ __nv_bfloat16 g_wqkv[3 * Dc * Dc];
__device__ __nv_bfloat16 g_wout[Dc * Dc];
__device__ __nv_bfloat16 g_wfc1[HIDc * Dc];
__device__ __nv_bfloat16 g_wfc2[Dc * HIDc];

// ---------------------------------------------------------------------------
// helpers
// ---------------------------------------------------------------------------
__device__ __forceinline__ uint32_t packbf(float a, float b)
{
    union { __nv_bfloat162 h; uint32_t u; } p;
    p.h = __float22bfloat162_rn(make_float2(a, b));
    return p.u;
}

__device__ __forceinline__ void ldsm4(uint32_t* r, uint32_t addr)
{
    asm volatile("ldmatrix.sync.aligned.m8n8.x4.shared.b16 {%0,%1,%2,%3}, [%4];"
                 : "=r"(r[0]), "=r"(r[1]), "=r"(r[2]), "=r"(r[3]) : "r"(addr));
}

__device__ __forceinline__ void ldsm4t(uint32_t* r, uint32_t addr)
{
    asm volatile("ldmatrix.sync.aligned.m8n8.x4.trans.shared.b16 {%0,%1,%2,%3}, [%4];"
                 : "=r"(r[0]), "=r"(r[1]), "=r"(r[2]), "=r"(r[3]) : "r"(addr));
}

__device__ __forceinline__ void mma_bf16(float (&c)[4], const uint32_t* a,
                                         uint32_t b0, uint32_t b1)
{
    asm volatile(
        "mma.sync.aligned.m16n8k16.row.col.f32.bf16.bf16.f32 "
        "{%0,%1,%2,%3}, {%4,%5,%6,%7}, {%8,%9}, {%0,%1,%2,%3};"
        : "+f"(c[0]), "+f"(c[1]), "+f"(c[2]), "+f"(c[3])
        : "r"(a[0]), "r"(a[1]), "r"(a[2]), "r"(a[3]), "r"(b0), "r"(b1));
}

__device__ __forceinline__ float gelu_exact(float v)
{
    return 0.5f * v * (1.0f + erff(v * 0.70710678118654752f));
}

__device__ __forceinline__ void mbar_init(uint32_t a, uint32_t cnt)
{
    asm volatile("mbarrier.init.shared.b64 [%0], %1;" :: "r"(a), "r"(cnt) : "memory");
}
__device__ __forceinline__ void mbar_expect_tx(uint32_t a, uint32_t bytes)
{
    asm volatile("mbarrier.arrive.expect_tx.shared.b64 _, [%0], %1;"
                 :: "r"(a), "r"(bytes) : "memory");
}
__device__ __forceinline__ void mbar_wait(uint32_t a, uint32_t ph)
{
    asm volatile(
        "{\n\t.reg .pred P;\n"
        "LW%=:\n\tmbarrier.try_wait.parity.acquire.cta.shared::cta.b64 P, [%0], %1, 0x989680;\n"
        "\t@P bra LD%=;\n\tbra LW%=;\nLD%=:\n\t}"
        :: "r"(a), "r"(ph) : "memory");
}
__device__ __forceinline__ void bulk_g2s(uint32_t dst, const void* src,
                                         uint32_t bytes, uint32_t mbar)
{
    asm volatile(
        "cp.async.bulk.shared::cluster.global.mbarrier::complete_tx::bytes "
        "[%0], [%1], %2, [%3];"
        :: "r"(dst), "l"(src), "r"(bytes), "r"(mbar) : "memory");
}

// ---------------------------------------------------------------------------
// fp32 -> bf16 weight conversion into tiled images (single launch)
// ---------------------------------------------------------------------------
__device__ __forceinline__ void emit_w(const float* __restrict__ src,
                                       __nv_bfloat16* __restrict__ dst,
                                       int i, int Kd)
{
    int n = i / Kd, k = i - n * Kd;
    float4 v0 = *(const float4*)(src + i);
    float4 v1 = *(const float4*)(src + i + 4);
    union { __nv_bfloat162 h[4]; uint4 u; } pk;
    pk.h[0] = __float22bfloat162_rn(make_float2(v0.x, v0.y));
    pk.h[1] = __float22bfloat162_rn(make_float2(v0.z, v0.w));
    pk.h[2] = __float22bfloat162_rn(make_float2(v1.x, v1.y));
    pk.h[3] = __float22bfloat162_rn(make_float2(v1.z, v1.w));
    int KT = Kd >> 6;
    size_t e = ((size_t)((n >> 7) * KT + (k >> 6))) * 8192 + (n & 127) * 64
             + ((((k >> 3) & 7) ^ (n & 7)) << 3);
    *(uint4*)(dst + e) = pk.u;
}

__global__ void __launch_bounds__(256) f2bf_all_kernel(const float* __restrict__ w0,
                                                       const float* __restrict__ w1,
                                                       const float* __restrict__ w2,
                                                       const float* __restrict__ w3,
                                                       __nv_bfloat16* __restrict__ o0,
                                                       __nv_bfloat16* __restrict__ o1,
                                                       __nv_bfloat16* __restrict__ o2,
                                                       __nv_bfloat16* __restrict__ o3)
{
    int u = blockIdx.x * 256 + threadIdx.x;
    if (u < 24576)      emit_w(w0, o0, u * 8, 256);
    else if (u < 32768) emit_w(w1, o1, (u - 24576) * 8, 256);
    else if (u < 49152) emit_w(w2, o2, (u - 32768) * 8, 256);
    else                emit_w(w3, o3, (u - 49152) * 8, 512);
}

// ---------------------------------------------------------------------------
// LayerNorm: one warp per row; writes tiled bf16 image (K=256 -> KT=4)
// ---------------------------------------------------------------------------
__global__ void __launch_bounds__(256) ln_bf_kernel(const float* __restrict__ x,
                                                    const float* __restrict__ g,
                                                    const float* __restrict__ b,
                                                    __nv_bfloat16* __restrict__ out)
{
    int warp = threadIdx.x >> 5, lane = threadIdx.x & 31;
    size_t row = (size_t)blockIdx.x * 8 + warp;
    const float* xr = x + row * Dc;
    int c = lane * 8;
    float4 v0 = *(const float4*)(xr + c);
    float4 v1 = *(const float4*)(xr + c + 4);
    float sum = v0.x + v0.y + v0.z + v0.w + v1.x + v1.y + v1.z + v1.w;
    float sq  = v0.x*v0.x + v0.y*v0.y + v0.z*v0.z + v0.w*v0.w
              + v1.x*v1.x + v1.y*v1.y + v1.z*v1.z + v1.w*v1.w;
    #pragma unroll
    for (int off = 16; off; off >>= 1) {
        sum += __shfl_xor_sync(0xffffffff, sum, off);
        sq  += __shfl_xor_sync(0xffffffff, sq,  off);
    }
    float mu  = sum * (1.0f / 256.0f);
    float var = sq * (1.0f / 256.0f) - mu * mu;
    float rs  = rsqrtf(var + 1e-5f);
    float4 g0 = *(const float4*)(g + c), g1 = *(const float4*)(g + c + 4);
    float4 b0 = *(const float4*)(b + c), b1 = *(const float4*)(b + c + 4);
    union { __nv_bfloat162 h[4]; uint4 u; } pk;
    pk.h[0] = __float22bfloat162_rn(make_float2((v0.x - mu) * rs * g0.x + b0.x,
                                                (v0.y - mu) * rs * g0.y + b0.y));
    pk.h[1] = __float22bfloat162_rn(make_float2((v0.z - mu) * rs * g0.z + b0.z,
                                                (v0.w - mu) * rs * g0.w + b0.w));
    pk.h[2] = __float22bfloat162_rn(make_float2((v1.x - mu) * rs * g1.x + b1.x,
                                                (v1.y - mu) * rs * g1.y + b1.y));
    pk.h[3] = __float22bfloat162_rn(make_float2((v1.z - mu) * rs * g1.z + b1.z,
                                                (v1.w - mu) * rs * g1.w + b1.w));
    int kt = lane >> 3;
    int cs = (lane & 7) ^ ((int)row & 7);
    size_t e = ((size_t)((row >> 7) * 4 + kt)) * 8192 + (row & 127) * 64 + (cs << 3);
    *(uint4*)(out + e) = pk.u;
}

// ---------------------------------------------------------------------------
// bf16 GEMM on tiled images: C = A @ B^T + bias (+epilogue)
// CTA 128x128, BK=64, 3-stage cp.async.bulk ring: 32 KB/stage (A 16K + B 16K).
// ---------------------------------------------------------------------------
#define BGSMEM (3 * 32768)

template <int EPI, int OBF, int K, int OTILED, int OKT>
__global__ void __launch_bounds__(256, 2) bgemm_kernel(const __nv_bfloat16* __restrict__ Aimg,
                                                       const __nv_bfloat16* __restrict__ Bimg,
                                                       const float* __restrict__ bias,
                                                       const float* __restrict__ resid,
                                                       void* __restrict__ Cv,
                                                       int M, int N)
{
    extern __shared__ __nv_bfloat16 dyn[];
    __shared__ uint64_t mbar_s[3];

    constexpr int KT = K >> 6;
    int tid = threadIdx.x, lane = tid & 31, warp = tid >> 5;
    int wm = warp >> 2, wn = warp & 3;
    int m0 = blockIdx.y * 128, n0 = blockIdx.x * 128;

    uint32_t sbase = (uint32_t)__cvta_generic_to_shared(dyn);
    uint32_t mb0 = (uint32_t)__cvta_generic_to_shared(&mbar_s[0]);

    const __nv_bfloat16* Asrc = Aimg + (size_t)blockIdx.y * KT * 8192;
    const __nv_bfloat16* Bsrc = Bimg + (size_t)blockIdx.x * KT * 8192;

    if (tid == 0) {
        mbar_init(mb0, 1);
        mbar_init(mb0 + 8, 1);
        mbar_init(mb0 + 16, 1);
    }
    __syncthreads();
    if (tid == 0) {
        #pragma unroll
        for (int s = 0; s < 3 && s < KT; s++) {
            mbar_expect_tx(mb0 + s * 8, 32768);
            bulk_g2s(sbase + s * 32768, Asrc + s * 8192, 16384, mb0 + s * 8);
            bulk_g2s(sbase + s * 32768 + 16384, Bsrc + s * 8192, 16384, mb0 + s * 8);
        }
    }

    int sk = lane & 7;
    int ac = lane >> 4;            // A chunk select
    int br = (lane & 7) | (((lane >> 4) & 1) << 3);
    int bc = (lane >> 3) & 1;      // B chunk select
    uint32_t aRow[4], bRow[2];
    #pragma unroll
    for (int mt = 0; mt < 4; mt++)
        aRow[mt] = (wm * 64 + mt * 16 + (lane & 15)) * 128;
    #pragma unroll
    for (int p = 0; p < 2; p++)
        bRow[p] = (wn * 32 + p * 16 + br) * 128;

    float acc[4][4][4] = {};

    #pragma unroll
    for (int kt = 0; kt < KT; kt++) {
        const int s = kt % 3;
        mbar_wait(mb0 + s * 8, (kt / 3) & 1);
        uint32_t aB = sbase + s * 32768;
        uint32_t bB = aB + 16384;
        #pragma unroll
        for (int kk = 0; kk < 4; kk++) {
            uint32_t ca = (uint32_t)(((kk * 2 + ac) ^ sk) << 4);
            uint32_t cb = (uint32_t)(((kk * 2 + bc) ^ sk) << 4);
            uint32_t a[4][4], b[2][4];
            #pragma unroll
            for (int mt = 0; mt < 4; mt++)
                ldsm4(a[mt], aB + aRow[mt] + ca);
            #pragma unroll
            for (int p = 0; p < 2; p++)
                ldsm4(b[p], bB + bRow[p] + cb);
            #pragma unroll
            for (int mt = 0; mt < 4; mt++) {
                mma_bf16(acc[mt][0], a[mt], b[0][0], b[0][1]);
                mma_bf16(acc[mt][1], a[mt], b[0][2], b[0][3]);
                mma_bf16(acc[mt][2], a[mt], b[1][0], b[1][1]);
                mma_bf16(acc[mt][3], a[mt], b[1][2], b[1][3]);
            }
        }
        __syncthreads();
        if (tid == 0 && kt + 3 < KT) {
            mbar_expect_tx(mb0 + s * 8, 32768);
            bulk_g2s(sbase + s * 32768, Asrc + (kt + 3) * 8192, 16384, mb0 + s * 8);
            bulk_g2s(sbase + s * 32768 + 16384, Bsrc + (kt + 3) * 8192, 16384, mb0 + s * 8);
        }
    }

    float* Cf = (float*)Cv;
    __nv_bfloat16* Cb = (__nv_bfloat16*)Cv;
    int g = lane >> 2, t = lane & 3;
    #pragma unroll
    for (int mt = 0; mt < 4; mt++) {
        size_t r0 = (size_t)m0 + wm * 64 + mt * 16 + g;
        size_t r1 = r0 + 8;
        #pragma unroll
        for (int nt = 0; nt < 4; nt++) {
            int col = n0 + wn * 32 + nt * 8 + 2 * t;
            float b0 = bias[col], b1 = bias[col + 1];
            float v00 = acc[mt][nt][0] + b0, v01 = acc[mt][nt][1] + b1;
            float v10 = acc[mt][nt][2] + b0, v11 = acc[mt][nt][3] + b1;
            if (EPI == 1) {
                v00 = gelu_exact(v00); v01 = gelu_exact(v01);
                v10 = gelu_exact(v10); v11 = gelu_exact(v11);
            }
            if (EPI == 2) {
                float2 q0 = *(const float2*)&resid[r0 * N + col];
                float2 q1 = *(const float2*)&resid[r1 * N + col];
                v00 += q0.x; v01 += q0.y; v10 += q1.x; v11 += q1.y;
            }
            if (OTILED) {
                int kto = col >> 6;
                int ci  = (col >> 3) & 7;
                size_t e0 = ((size_t)((r0 >> 7) * OKT + kto)) * 8192 + (r0 & 127) * 64
                          + (((size_t)(ci ^ ((int)r0 & 7))) << 3) + (col & 7);
                size_t e1 = ((size_t)((r1 >> 7) * OKT + kto)) * 8192 + (r1 & 127) * 64
                          + (((size_t)(ci ^ ((int)r1 & 7))) << 3) + (col & 7);
                *(uint32_t*)&Cb[e0] = packbf(v00, v01);
                *(uint32_t*)&Cb[e1] = packbf(v10, v11);
            } else if (OBF) {
                *(uint32_t*)&Cb[r0 * N + col] = packbf(v00, v01);
                *(uint32_t*)&Cb[r1 * N + col] = packbf(v10, v11);
            } else {
                *(float2*)&Cf[r0 * N + col] = make_float2(v00, v01);
                *(float2*)&Cf[r1 * N + col] = make_float2(v10, v11);
            }
        }
    }
}

// ---------------------------------------------------------------------------
// Windowed attention (bf16 mma). qkv row-major in; o written as tiled image.
// V stored straight (pitch 40) and consumed via ldmatrix.trans.
// ---------------------------------------------------------------------------
__device__ __forceinline__ int rowmap(int wi, int l)
{
    int b   = wi >> 7;
    int rem = wi & 127;
    int hb  = rem >> 4;
    int wb  = rem & 15;
    int r   = l / WW;
    int c   = l - r * WW;
    return b * Nc + (hb * WH + r) * Wc + wb * WW + c;
}

__global__ void __launch_bounds__(160) attn_kernel(const __nv_bfloat16* __restrict__ qkv,
                                                   __nv_bfloat16* __restrict__ o)
{
    __shared__ __nv_bfloat16 sQ[80 * 40];
    __shared__ __nv_bfloat16 sK[80 * 40];
    __shared__ __nv_bfloat16 sV[80 * 40];

    int bx = blockIdx.x, wi = bx >> 3, h = bx & 7;
    int tid = threadIdx.x, lane = tid & 31, w = tid >> 5;

    int lrow = tid >> 3, lseg = tid & 7;
    #pragma unroll
    for (int r0 = 0; r0 < 80; r0 += 20) {
        int l = r0 + lrow;
        uint2 qv = make_uint2(0, 0), kv = qv, vv = qv;
        if (l < L77) {
            int grow = rowmap(wi, l);
            const __nv_bfloat16* base = qkv + (size_t)grow * (3 * Dc) + h * HD + lseg * 4;
            qv = *(const uint2*)(base);
            kv = *(const uint2*)(base + Dc);
            vv = *(const uint2*)(base + 2 * Dc);
        }
        *(uint2*)&sQ[l * 40 + lseg * 4] = qv;
        *(uint2*)&sK[l * 40 + lseg * 4] = kv;
        *(uint2*)&sV[l * 40 + lseg * 4] = vv;
    }
    __syncthreads();

    int a_row = lane & 15;
    int a_c   = lane >> 4;
    int b_row = (lane & 7) | (((lane >> 4) & 1) << 3);
    int b_c   = (lane >> 3) & 1;
    int g = lane >> 2, t = lane & 3;

    uint32_t aQ = (uint32_t)__cvta_generic_to_shared(&sQ[(w * 16 + a_row) * 40]) + a_c * 16;
    uint32_t bK = (uint32_t)__cvta_generic_to_shared(&sK[b_row * 40]) + b_c * 16;
    uint32_t bV = (uint32_t)__cvta_generic_to_shared(sV)
                + ((lane & 15) * 40 + ((lane >> 4) << 3)) * 2;

    float s[10][4] = {};
    uint32_t aq[2][4];
    ldsm4(aq[0], aQ);
    ldsm4(aq[1], aQ + 32);
    #pragma unroll
    for (int kk = 0; kk < 2; kk++) {
        #pragma unroll
        for (int p = 0; p < 5; p++) {
            uint32_t b[4];
            ldsm4(b, bK + p * 1280 + kk * 32);
            mma_bf16(s[2 * p],     aq[kk], b[0], b[1]);
            mma_bf16(s[2 * p + 1], aq[kk], b[2], b[3]);
        }
    }

    if (72 + 2 * t >= L77) { s[9][0] = -1e30f; s[9][2] = -1e30f; }
    if (73 + 2 * t >= L77) { s[9][1] = -1e30f; s[9][3] = -1e30f; }

    const float scale = 0.17677669529663687f;
    float mx0 = -1e30f, mx1 = -1e30f;
    #pragma unroll
    for (int nt = 0; nt < 10; nt++) {
        mx0 = fmaxf(mx0, fmaxf(s[nt][0], s[nt][1]));
        mx1 = fmaxf(mx1, fmaxf(s[nt][2], s[nt][3]));
    }
    mx0 = fmaxf(mx0, __shfl_xor_sync(0xffffffff, mx0, 1));
    mx0 = fmaxf(mx0, __shfl_xor_sync(0xffffffff, mx0, 2));
    mx1 = fmaxf(mx1, __shfl_xor_sync(0xffffffff, mx1, 1));
    mx1 = fmaxf(mx1, __shfl_xor_sync(0xffffffff, mx1, 2));
    float ms0 = mx0 * scale, ms1 = mx1 * scale;

    float e[10][4];
    float sum0 = 0.f, sum1 = 0.f;
    #pragma unroll
    for (int nt = 0; nt < 10; nt++) {
        e[nt][0] = __expf(fmaf(s[nt][0], scale, -ms0));
        e[nt][1] = __expf(fmaf(s[nt][1], scale, -ms0));
        e[nt][2] = __expf(fmaf(s[nt][2], scale, -ms1));
        e[nt][3] = __expf(fmaf(s[nt][3], scale, -ms1));
        sum0 += e[nt][0] + e[nt][1];
        sum1 += e[nt][2] + e[nt][3];
    }
    sum0 += __shfl_xor_sync(0xffffffff, sum0, 1);
    sum0 += __shfl_xor_sync(0xffffffff, sum0, 2);
    sum1 += __shfl_xor_sync(0xffffffff, sum1, 1);
    sum1 += __shfl_xor_sync(0xffffffff, sum1, 2);
    float inv0 = 1.0f / sum0, inv1 = 1.0f / sum1;

    uint32_t pa[5][4];
    #pragma unroll
    for (int kf = 0; kf < 5; kf++) {
        pa[kf][0] = packbf(e[2 * kf][0],     e[2 * kf][1]);
        pa[kf][1] = packbf(e[2 * kf][2],     e[2 * kf][3]);
        pa[kf][2] = packbf(e[2 * kf + 1][0], e[2 * kf + 1][1]);
        pa[kf][3] = packbf(e[2 * kf + 1][2], e[2 * kf + 1][3]);
    }

    float oa[4][4] = {};
    #pragma unroll
    for (int kf = 0; kf < 5; kf++) {
        #pragma unroll
        for (int vt = 0; vt < 2; vt++) {
            uint32_t b[4];
            ldsm4t(b, bV + (kf * 16 * 40 + vt * 16) * 2);
            mma_bf16(oa[2 * vt],     pa[kf], b[0], b[1]);
            mma_bf16(oa[2 * vt + 1], pa[kf], b[2], b[3]);
        }
    }

    int r0 = w * 16 + g, r1 = r0 + 8;
    if (r0 < L77) {
        int grow = rowmap(wi, r0);
        size_t base = ((size_t)((grow >> 7) * 4 + (h >> 1))) * 8192 + (grow & 127) * 64;
        int rk = grow & 7;
        #pragma unroll
        for (int nt = 0; nt < 4; nt++) {
            int ci = ((h & 1) * 4 + nt) ^ rk;
            *(uint32_t*)&o[base + ci * 8 + 2 * t] =
                packbf(oa[nt][0] * inv0, oa[nt][1] * inv0);
        }
    }
    if (r1 < L77) {
        int grow = rowmap(wi, r1);
        size_t base = ((size_t)((grow >> 7) * 4 + (h >> 1))) * 8192 + (grow & 127) * 64;
        int rk = grow & 7;
        #pragma unroll
        for (int nt = 0; nt < 4; nt++) {
            int ci = ((h & 1) * 4 + nt) ^ rk;
            *(uint32_t*)&o[base + ci * 8 + 2 * t] =
                packbf(oa[nt][2] * inv1, oa[nt][3] * inv1);
        }
    }
}

// ---------------------------------------------------------------------------
// Launch
// ---------------------------------------------------------------------------
extern "C" void kernel_launch(void* const* d_in, const int* in_sizes, int n_in,
                              void* d_out, int out_size)
{
    const float* x         = (const float*)d_in[0];
    const float* norm1_g   = (const float*)d_in[1];
    const float* norm1_b   = (const float*)d_in[2];
    const float* in_proj_w = (const float*)d_in[3];
    const float* in_proj_b = (const float*)d_in[4];
    const float* out_w     = (const float*)d_in[5];
    const float* out_b     = (const float*)d_in[6];
    const float* norm2_g   = (const float*)d_in[7];
    const float* norm2_b   = (const float*)d_in[8];
    const float* fc1_w     = (const float*)d_in[9];
    const float* fc1_b     = (const float*)d_in[10];
    const float* fc2_w     = (const float*)d_in[11];
    const float* fc2_b     = (const float*)d_in[12];
    float* out = (float*)d_out;

    __nv_bfloat16 *p_xnb, *p_qkvb, *p_wqkv, *p_wout, *p_wfc1, *p_wfc2;
    float* p_y;
    cudaGetSymbolAddress((void**)&p_xnb,  g_xnb);
    cudaGetSymbolAddress((void**)&p_qkvb, g_qkvb);
    cudaGetSymbolAddress((void**)&p_y,    g_y);
    cudaGetSymbolAddress((void**)&p_wqkv, g_wqkv);
    cudaGetSymbolAddress((void**)&p_wout, g_wout);
    cudaGetSymbolAddress((void**)&p_wfc1, g_wfc1);
    cudaGetSymbolAddress((void**)&p_wfc2, g_wfc2);

    cudaFuncSetAttribute((const void*)bgemm_kernel<0, 1, 256, 0, 0>,
                         cudaFuncAttributeMaxDynamicSharedMemorySize, BGSMEM);
    cudaFuncSetAttribute((const void*)bgemm_kernel<2, 0, 256, 0, 0>,
                         cudaFuncAttributeMaxDynamicSharedMemorySize, BGSMEM);
    cudaFuncSetAttribute((const void*)bgemm_kernel<1, 1, 256, 1, 8>,
                         cudaFuncAttributeMaxDynamicSharedMemorySize, BGSMEM);
    cudaFuncSetAttribute((const void*)bgemm_kernel<2, 0, 512, 0, 0>,
                         cudaFuncAttributeMaxDynamicSharedMemorySize, BGSMEM);

    // 0) weights -> tiled bf16 images
    f2bf_all_kernel<<<256, 256>>>(in_proj_w, out_w, fc1_w, fc2_w,
                                  p_wqkv, p_wout, p_wfc1, p_wfc2);

    // 1) LN1: x -> xn image
    ln_bf_kernel<<<MROWS / 8, 256>>>(x, norm1_g, norm1_b, p_xnb);

    // 2) QKV = xn @ Wqkv^T + b  (row-major bf16 out)
    {
        dim3 grid(768 / 128, MROWS / 128);
        bgemm_kernel<0, 1, 256, 0, 0><<<grid, 256, BGSMEM>>>(
            p_xnb, p_wqkv, in_proj_b, nullptr, p_qkvb, MROWS, 3 * Dc);
    }

    // 3) attention -> o image (reuse g_xnb)
    attn_kernel<<<NWIN * HEADS, 160>>>(p_qkvb, p_xnb);

    // 4) y = x + o @ Wout^T + b  (fp32 row-major)
    {
        dim3 grid(Dc / 128, MROWS / 128);
        bgemm_kernel<2, 0, 256, 0, 0><<<grid, 256, BGSMEM>>>(
            p_xnb, p_wout, out_b, x, p_y, MROWS, Dc);
    }

    // 5) LN2: y -> yn image (into g_qkvb[0 : M*256))
    ln_bf_kernel<<<MROWS / 8, 256>>>(p_y, norm2_g, norm2_b, p_qkvb);

    // 6) hmid = gelu(yn @ Wfc1^T + b)  (tiled image out, OKT=8)
    __nv_bfloat16* p_yn   = p_qkvb;
    __nv_bfloat16* p_hmid = p_qkvb + (size_t)MROWS * Dc;
    {
        dim3 grid(HIDc / 128, MROWS / 128);
        bgemm_kernel<1, 1, 256, 1, 8><<<grid, 256, BGSMEM>>>(
            p_yn, p_wfc1, fc1_b, nullptr, p_hmid, MROWS, HIDc);
    }

    // 7) out = y + hmid @ Wfc2^T + b  (fp32 row-major)
    {
        dim3 grid(Dc / 128, MROWS / 128);
        bgemm_kernel<2, 0, 512, 0, 0><<<grid, 256, BGSMEM>>>(
            p_hmid, p_wfc2, fc2_b, p_y, out, MROWS, Dc);
    }
}

// round 10
// speedup vs baseline: 3.2831x; 1.0077x over previous
#include <cuda_runtime.h>
#include <cuda_bf16.h>
#include <math.h>
#include <stdint.h>

// Problem constants
#define Bc    8
#define Nc    9856
#define Dc    256
#define HEADS 8
#define HD    32
#define WH    7
#define WW    11
#define L77   77
#define HIDc  512
#define Hc    56
#define Wc    176
#define NH    8
#define NWn   16
#define MROWS (Bc * Nc)       // 78848
#define NWIN  (Bc * NH * NWn) // 1024

// Tiled image layout: tile (rb=r/128, kt=k/64) is an 8192-elem (16 KB) block at
// ((rb*(K/64))+kt)*8192; row r%128 = 64 elems (128 B); 16B chunk c at (c ^ (row&7)).

// ---------------------------------------------------------------------------
// Scratch (device globals)
// ---------------------------------------------------------------------------
__device__ __nv_bfloat16 g_xnb[(size_t)MROWS * Dc];        // xn image; later o image
__device__ __nv_bfloat16 g_qkvb[(size_t)MROWS * 3 * Dc];   // qkv row-major; later [yn img | hmid img]
__device__ float         g_y[(size_t)MROWS * Dc];          // x + attn residual
__device__ __nv_bfloat16 g_wqkv[3 * Dc * Dc];
__device__ __nv_bfloat16 g_wout[Dc * Dc];
__device__ __nv_bfloat16 g_wfc1[HIDc * Dc];
__device__ __nv_bfloat16 g_wfc2[Dc * HIDc];

// ---------------------------------------------------------------------------
// helpers
// ---------------------------------------------------------------------------
__device__ __forceinline__ uint32_t packbf(float a, float b)
{
    union { __nv_bfloat162 h; uint32_t u; } p;
    p.h = __float22bfloat162_rn(make_float2(a, b));
    return p.u;
}

__device__ __forceinline__ void ldsm4(uint32_t* r, uint32_t addr)
{
    asm volatile("ldmatrix.sync.aligned.m8n8.x4.shared.b16 {%0,%1,%2,%3}, [%4];"
                 : "=r"(r[0]), "=r"(r[1]), "=r"(r[2]), "=r"(r[3]) : "r"(addr));
}

__device__ __forceinline__ void ldsm4t(uint32_t* r, uint32_t addr)
{
    asm volatile("ldmatrix.sync.aligned.m8n8.x4.trans.shared.b16 {%0,%1,%2,%3}, [%4];"
                 : "=r"(r[0]), "=r"(r[1]), "=r"(r[2]), "=r"(r[3]) : "r"(addr));
}

__device__ __forceinline__ void mma_bf16(float (&c)[4], const uint32_t* a,
                                         uint32_t b0, uint32_t b1)
{
    asm volatile(
        "mma.sync.aligned.m16n8k16.row.col.f32.bf16.bf16.f32 "
        "{%0,%1,%2,%3}, {%4,%5,%6,%7}, {%8,%9}, {%0,%1,%2,%3};"
        : "+f"(c[0]), "+f"(c[1]), "+f"(c[2]), "+f"(c[3])
        : "r"(a[0]), "r"(a[1]), "r"(a[2]), "r"(a[3]), "r"(b0), "r"(b1));
}

__device__ __forceinline__ float gelu_exact(float v)
{
    return 0.5f * v * (1.0f + erff(v * 0.70710678118654752f));
}

__device__ __forceinline__ void mbar_init(uint32_t a, uint32_t cnt)
{
    asm volatile("mbarrier.init.shared.b64 [%0], %1;" :: "r"(a), "r"(cnt) : "memory");
}
__device__ __forceinline__ void mbar_expect_tx(uint32_t a, uint32_t bytes)
{
    asm volatile("mbarrier.arrive.expect_tx.shared.b64 _, [%0], %1;"
                 :: "r"(a), "r"(bytes) : "memory");
}
__device__ __forceinline__ void mbar_wait(uint32_t a, uint32_t ph)
{
    asm volatile(
        "{\n\t.reg .pred P;\n"
        "LW%=:\n\tmbarrier.try_wait.parity.acquire.cta.shared::cta.b64 P, [%0], %1, 0x989680;\n"
        "\t@P bra LD%=;\n\tbra LW%=;\nLD%=:\n\t}"
        :: "r"(a), "r"(ph) : "memory");
}
__device__ __forceinline__ void bulk_g2s(uint32_t dst, const void* src,
                                         uint32_t bytes, uint32_t mbar)
{
    asm volatile(
        "cp.async.bulk.shared::cluster.global.mbarrier::complete_tx::bytes "
        "[%0], [%1], %2, [%3];"
        :: "r"(dst), "l"(src), "r"(bytes), "r"(mbar) : "memory");
}

// ---------------------------------------------------------------------------
// weight conversion helper (fp32 row-major [N,K] -> tiled bf16 image)
// ---------------------------------------------------------------------------
__device__ __forceinline__ void emit_w(const float* __restrict__ src,
                                       __nv_bfloat16* __restrict__ dst,
                                       int i, int Kd)
{
    int n = i / Kd, k = i - n * Kd;
    float4 v0 = *(const float4*)(src + i);
    float4 v1 = *(const float4*)(src + i + 4);
    union { __nv_bfloat162 h[4]; uint4 u; } pk;
    pk.h[0] = __float22bfloat162_rn(make_float2(v0.x, v0.y));
    pk.h[1] = __float22bfloat162_rn(make_float2(v0.z, v0.w));
    pk.h[2] = __float22bfloat162_rn(make_float2(v1.x, v1.y));
    pk.h[3] = __float22bfloat162_rn(make_float2(v1.z, v1.w));
    int KT = Kd >> 6;
    size_t e = ((size_t)((n >> 7) * KT + (k >> 6))) * 8192 + (n & 127) * 64
             + ((((k >> 3) & 7) ^ (n & 7)) << 3);
    *(uint4*)(dst + e) = pk.u;
}

// ---------------------------------------------------------------------------
// LayerNorm body (one warp per row of 256; writes tiled bf16 image, KT=4)
// ---------------------------------------------------------------------------
__device__ __forceinline__ void ln_row(const float* __restrict__ x,
                                       const float* __restrict__ g,
                                       const float* __restrict__ b,
                                       __nv_bfloat16* __restrict__ out,
                                       size_t row, int lane)
{
    const float* xr = x + row * Dc;
    int c = lane * 8;
    float4 v0 = *(const float4*)(xr + c);
    float4 v1 = *(const float4*)(xr + c + 4);
    float sum = v0.x + v0.y + v0.z + v0.w + v1.x + v1.y + v1.z + v1.w;
    float sq  = v0.x*v0.x + v0.y*v0.y + v0.z*v0.z + v0.w*v0.w
              + v1.x*v1.x + v1.y*v1.y + v1.z*v1.z + v1.w*v1.w;
    #pragma unroll
    for (int off = 16; off; off >>= 1) {
        sum += __shfl_xor_sync(0xffffffff, sum, off);
        sq  += __shfl_xor_sync(0xffffffff, sq,  off);
    }
    float mu  = sum * (1.0f / 256.0f);
    float var = sq * (1.0f / 256.0f) - mu * mu;
    float rs  = rsqrtf(var + 1e-5f);
    float4 g0 = *(const float4*)(g + c), g1 = *(const float4*)(g + c + 4);
    float4 b0 = *(const float4*)(b + c), b1 = *(const float4*)(b + c + 4);
    union { __nv_bfloat162 h[4]; uint4 u; } pk;
    pk.h[0] = __float22bfloat162_rn(make_float2((v0.x - mu) * rs * g0.x + b0.x,
                                                (v0.y - mu) * rs * g0.y + b0.y));
    pk.h[1] = __float22bfloat162_rn(make_float2((v0.z - mu) * rs * g0.z + b0.z,
                                                (v0.w - mu) * rs * g0.w + b0.w));
    pk.h[2] = __float22bfloat162_rn(make_float2((v1.x - mu) * rs * g1.x + b1.x,
                                                (v1.y - mu) * rs * g1.y + b1.y));
    pk.h[3] = __float22bfloat162_rn(make_float2((v1.z - mu) * rs * g1.z + b1.z,
                                                (v1.w - mu) * rs * g1.w + b1.w));
    int kt = lane >> 3;
    int cs = (lane & 7) ^ ((int)row & 7);
    size_t e = ((size_t)((row >> 7) * 4 + kt)) * 8192 + (row & 127) * 64 + (cs << 3);
    *(uint4*)(out + e) = pk.u;
}

// Standalone LN (used for LN2)
__global__ void __launch_bounds__(256) ln_bf_kernel(const float* __restrict__ x,
                                                    const float* __restrict__ g,
                                                    const float* __restrict__ b,
                                                    __nv_bfloat16* __restrict__ out)
{
    int warp = threadIdx.x >> 5, lane = threadIdx.x & 31;
    ln_row(x, g, b, out, (size_t)blockIdx.x * 8 + warp, lane);
}

// Merged: blocks [0,256) convert the 4 weight matrices; blocks [256,...) do LN1.
__global__ void __launch_bounds__(256) prep_kernel(const float* __restrict__ x,
                                                   const float* __restrict__ g,
                                                   const float* __restrict__ b,
                                                   __nv_bfloat16* __restrict__ out,
                                                   const float* __restrict__ w0,
                                                   const float* __restrict__ w1,
                                                   const float* __restrict__ w2,
                                                   const float* __restrict__ w3,
                                                   __nv_bfloat16* __restrict__ o0,
                                                   __nv_bfloat16* __restrict__ o1,
                                                   __nv_bfloat16* __restrict__ o2,
                                                   __nv_bfloat16* __restrict__ o3)
{
    if (blockIdx.x < 256) {
        int u = blockIdx.x * 256 + threadIdx.x;
        if (u < 24576)      emit_w(w0, o0, u * 8, 256);
        else if (u < 32768) emit_w(w1, o1, (u - 24576) * 8, 256);
        else if (u < 49152) emit_w(w2, o2, (u - 32768) * 8, 256);
        else                emit_w(w3, o3, (u - 49152) * 8, 512);
        return;
    }
    int warp = threadIdx.x >> 5, lane = threadIdx.x & 31;
    ln_row(x, g, b, out, (size_t)(blockIdx.x - 256) * 8 + warp, lane);
}

// ---------------------------------------------------------------------------
// bf16 GEMM on tiled images (R8 proven): CTA 128x128, BK=64,
// 3-stage cp.async.bulk ring: 32 KB/stage (A 16K + B 16K).
// ---------------------------------------------------------------------------
#define BGSMEM (3 * 32768)

template <int EPI, int OBF, int K, int OTILED, int OKT>
__global__ void __launch_bounds__(256, 2) bgemm_kernel(const __nv_bfloat16* __restrict__ Aimg,
                                                       const __nv_bfloat16* __restrict__ Bimg,
                                                       const float* __restrict__ bias,
                                                       const float* __restrict__ resid,
                                                       void* __restrict__ Cv,
                                                       int M, int N)
{
    extern __shared__ __nv_bfloat16 dyn[];
    __shared__ uint64_t mbar_s[3];

    constexpr int KT = K >> 6;
    int tid = threadIdx.x, lane = tid & 31, warp = tid >> 5;
    int wm = warp >> 2, wn = warp & 3;
    int m0 = blockIdx.y * 128, n0 = blockIdx.x * 128;

    uint32_t sbase = (uint32_t)__cvta_generic_to_shared(dyn);
    uint32_t mb0 = (uint32_t)__cvta_generic_to_shared(&mbar_s[0]);

    const __nv_bfloat16* Asrc = Aimg + (size_t)blockIdx.y * KT * 8192;
    const __nv_bfloat16* Bsrc = Bimg + (size_t)blockIdx.x * KT * 8192;

    if (tid == 0) {
        mbar_init(mb0, 1);
        mbar_init(mb0 + 8, 1);
        mbar_init(mb0 + 16, 1);
    }
    __syncthreads();
    if (tid == 0) {
        #pragma unroll
        for (int s = 0; s < 3 && s < KT; s++) {
            mbar_expect_tx(mb0 + s * 8, 32768);
            bulk_g2s(sbase + s * 32768, Asrc + s * 8192, 16384, mb0 + s * 8);
            bulk_g2s(sbase + s * 32768 + 16384, Bsrc + s * 8192, 16384, mb0 + s * 8);
        }
    }

    int sk = lane & 7;
    int ac = lane >> 4;            // A chunk select
    int br = (lane & 7) | (((lane >> 4) & 1) << 3);
    int bc = (lane >> 3) & 1;      // B chunk select
    uint32_t aRow[4], bRow[2];
    #pragma unroll
    for (int mt = 0; mt < 4; mt++)
        aRow[mt] = (wm * 64 + mt * 16 + (lane & 15)) * 128;
    #pragma unroll
    for (int p = 0; p < 2; p++)
        bRow[p] = (wn * 32 + p * 16 + br) * 128;

    float acc[4][4][4] = {};

    #pragma unroll
    for (int kt = 0; kt < KT; kt++) {
        const int s = kt % 3;
        mbar_wait(mb0 + s * 8, (kt / 3) & 1);
        uint32_t aB = sbase + s * 32768;
        uint32_t bB = aB + 16384;
        #pragma unroll
        for (int kk = 0; kk < 4; kk++) {
            uint32_t ca = (uint32_t)(((kk * 2 + ac) ^ sk) << 4);
            uint32_t cb = (uint32_t)(((kk * 2 + bc) ^ sk) << 4);
            uint32_t a[4][4], b[2][4];
            #pragma unroll
            for (int mt = 0; mt < 4; mt++)
                ldsm4(a[mt], aB + aRow[mt] + ca);
            #pragma unroll
            for (int p = 0; p < 2; p++)
                ldsm4(b[p], bB + bRow[p] + cb);
            #pragma unroll
            for (int mt = 0; mt < 4; mt++) {
                mma_bf16(acc[mt][0], a[mt], b[0][0], b[0][1]);
                mma_bf16(acc[mt][1], a[mt], b[0][2], b[0][3]);
                mma_bf16(acc[mt][2], a[mt], b[1][0], b[1][1]);
                mma_bf16(acc[mt][3], a[mt], b[1][2], b[1][3]);
            }
        }
        __syncthreads();
        if (tid == 0 && kt + 3 < KT) {
            mbar_expect_tx(mb0 + s * 8, 32768);
            bulk_g2s(sbase + s * 32768, Asrc + (kt + 3) * 8192, 16384, mb0 + s * 8);
            bulk_g2s(sbase + s * 32768 + 16384, Bsrc + (kt + 3) * 8192, 16384, mb0 + s * 8);
        }
    }

    float* Cf = (float*)Cv;
    __nv_bfloat16* Cb = (__nv_bfloat16*)Cv;
    int g = lane >> 2, t = lane & 3;
    #pragma unroll
    for (int mt = 0; mt < 4; mt++) {
        size_t r0 = (size_t)m0 + wm * 64 + mt * 16 + g;
        size_t r1 = r0 + 8;
        #pragma unroll
        for (int nt = 0; nt < 4; nt++) {
            int col = n0 + wn * 32 + nt * 8 + 2 * t;
            float b0 = bias[col], b1 = bias[col + 1];
            float v00 = acc[mt][nt][0] + b0, v01 = acc[mt][nt][1] + b1;
            float v10 = acc[mt][nt][2] + b0, v11 = acc[mt][nt][3] + b1;
            if (EPI == 1) {
                v00 = gelu_exact(v00); v01 = gelu_exact(v01);
                v10 = gelu_exact(v10); v11 = gelu_exact(v11);
            }
            if (EPI == 2) {
                float2 q0 = *(const float2*)&resid[r0 * N + col];
                float2 q1 = *(const float2*)&resid[r1 * N + col];
                v00 += q0.x; v01 += q0.y; v10 += q1.x; v11 += q1.y;
            }
            if (OTILED) {
                int kto = col >> 6;
                int ci  = (col >> 3) & 7;
                size_t e0 = ((size_t)((r0 >> 7) * OKT + kto)) * 8192 + (r0 & 127) * 64
                          + (((size_t)(ci ^ ((int)r0 & 7))) << 3) + (col & 7);
                size_t e1 = ((size_t)((r1 >> 7) * OKT + kto)) * 8192 + (r1 & 127) * 64
                          + (((size_t)(ci ^ ((int)r1 & 7))) << 3) + (col & 7);
                *(uint32_t*)&Cb[e0] = packbf(v00, v01);
                *(uint32_t*)&Cb[e1] = packbf(v10, v11);
            } else if (OBF) {
                *(uint32_t*)&Cb[r0 * N + col] = packbf(v00, v01);
                *(uint32_t*)&Cb[r1 * N + col] = packbf(v10, v11);
            } else {
                *(float2*)&Cf[r0 * N + col] = make_float2(v00, v01);
                *(float2*)&Cf[r1 * N + col] = make_float2(v10, v11);
            }
        }
    }
}

// ---------------------------------------------------------------------------
// Windowed attention (bf16 mma.sync). uint4 gather (16B/thread/matrix),
// V consumed via ldmatrix.trans, o written as tiled image.
// ---------------------------------------------------------------------------
__device__ __forceinline__ int rowmap(int wi, int l)
{
    int b   = wi >> 7;
    int rem = wi & 127;
    int hb  = rem >> 4;
    int wb  = rem & 15;
    int r   = l / WW;
    int c   = l - r * WW;
    return b * Nc + (hb * WH + r) * Wc + wb * WW + c;
}

__global__ void __launch_bounds__(160) attn_kernel(const __nv_bfloat16* __restrict__ qkv,
                                                   __nv_bfloat16* __restrict__ o)
{
    __shared__ __nv_bfloat16 sQ[80 * 40];
    __shared__ __nv_bfloat16 sK[80 * 40];
    __shared__ __nv_bfloat16 sV[80 * 40];

    int bx = blockIdx.x, wi = bx >> 3, h = bx & 7;
    int tid = threadIdx.x, lane = tid & 31, w = tid >> 5;

    // Gather: 40 rows per pass, 4 threads x 16B per row per matrix
    int lrow = tid >> 2, lseg = tid & 3;
    #pragma unroll
    for (int r0 = 0; r0 < 80; r0 += 40) {
        int l = r0 + lrow;
        uint4 qv = make_uint4(0, 0, 0, 0), kv = qv, vv = qv;
        if (l < L77) {
            int grow = rowmap(wi, l);
            const __nv_bfloat16* base = qkv + (size_t)grow * (3 * Dc) + h * HD + lseg * 8;
            qv = *(const uint4*)(base);
            kv = *(const uint4*)(base + Dc);
            vv = *(const uint4*)(base + 2 * Dc);
        }
        *(uint4*)&sQ[l * 40 + lseg * 8] = qv;
        *(uint4*)&sK[l * 40 + lseg * 8] = kv;
        *(uint4*)&sV[l * 40 + lseg * 8] = vv;
    }
    __syncthreads();

    int a_row = lane & 15;
    int a_c   = lane >> 4;
    int b_row = (lane & 7) | (((lane >> 4) & 1) << 3);
    int b_c   = (lane >> 3) & 1;
    int g = lane >> 2, t = lane & 3;

    uint32_t aQ = (uint32_t)__cvta_generic_to_shared(&sQ[(w * 16 + a_row) * 40]) + a_c * 16;
    uint32_t bK = (uint32_t)__cvta_generic_to_shared(&sK[b_row * 40]) + b_c * 16;
    uint32_t bV = (uint32_t)__cvta_generic_to_shared(sV)
                + ((lane & 15) * 40 + ((lane >> 4) << 3)) * 2;

    float s[10][4] = {};
    uint32_t aq[2][4];
    ldsm4(aq[0], aQ);
    ldsm4(aq[1], aQ + 32);
    #pragma unroll
    for (int kk = 0; kk < 2; kk++) {
        #pragma unroll
        for (int p = 0; p < 5; p++) {
            uint32_t b[4];
            ldsm4(b, bK + p * 1280 + kk * 32);
            mma_bf16(s[2 * p],     aq[kk], b[0], b[1]);
            mma_bf16(s[2 * p + 1], aq[kk], b[2], b[3]);
        }
    }

    if (72 + 2 * t >= L77) { s[9][0] = -1e30f; s[9][2] = -1e30f; }
    if (73 + 2 * t >= L77) { s[9][1] = -1e30f; s[9][3] = -1e30f; }

    const float scale = 0.17677669529663687f;
    float mx0 = -1e30f, mx1 = -1e30f;
    #pragma unroll
    for (int nt = 0; nt < 10; nt++) {
        mx0 = fmaxf(mx0, fmaxf(s[nt][0], s[nt][1]));
        mx1 = fmaxf(mx1, fmaxf(s[nt][2], s[nt][3]));
    }
    mx0 = fmaxf(mx0, __shfl_xor_sync(0xffffffff, mx0, 1));
    mx0 = fmaxf(mx0, __shfl_xor_sync(0xffffffff, mx0, 2));
    mx1 = fmaxf(mx1, __shfl_xor_sync(0xffffffff, mx1, 1));
    mx1 = fmaxf(mx1, __shfl_xor_sync(0xffffffff, mx1, 2));
    float ms0 = mx0 * scale, ms1 = mx1 * scale;

    float e[10][4];
    float sum0 = 0.f, sum1 = 0.f;
    #pragma unroll
    for (int nt = 0; nt < 10; nt++) {
        e[nt][0] = __expf(fmaf(s[nt][0], scale, -ms0));
        e[nt][1] = __expf(fmaf(s[nt][1], scale, -ms0));
        e[nt][2] = __expf(fmaf(s[nt][2], scale, -ms1));
        e[nt][3] = __expf(fmaf(s[nt][3], scale, -ms1));
        sum0 += e[nt][0] + e[nt][1];
        sum1 += e[nt][2] + e[nt][3];
    }
    sum0 += __shfl_xor_sync(0xffffffff, sum0, 1);
    sum0 += __shfl_xor_sync(0xffffffff, sum0, 2);
    sum1 += __shfl_xor_sync(0xffffffff, sum1, 1);
    sum1 += __shfl_xor_sync(0xffffffff, sum1, 2);
    float inv0 = 1.0f / sum0, inv1 = 1.0f / sum1;

    uint32_t pa[5][4];
    #pragma unroll
    for (int kf = 0; kf < 5; kf++) {
        pa[kf][0] = packbf(e[2 * kf][0],     e[2 * kf][1]);
        pa[kf][1] = packbf(e[2 * kf][2],     e[2 * kf][3]);
        pa[kf][2] = packbf(e[2 * kf + 1][0], e[2 * kf + 1][1]);
        pa[kf][3] = packbf(e[2 * kf + 1][2], e[2 * kf + 1][3]);
    }

    float oa[4][4] = {};
    #pragma unroll
    for (int kf = 0; kf < 5; kf++) {
        #pragma unroll
        for (int vt = 0; vt < 2; vt++) {
            uint32_t b[4];
            ldsm4t(b, bV + (kf * 16 * 40 + vt * 16) * 2);
            mma_bf16(oa[2 * vt],     pa[kf], b[0], b[1]);
            mma_bf16(oa[2 * vt + 1], pa[kf], b[2], b[3]);
        }
    }

    int r0 = w * 16 + g, r1 = r0 + 8;
    if (r0 < L77) {
        int grow = rowmap(wi, r0);
        size_t base = ((size_t)((grow >> 7) * 4 + (h >> 1))) * 8192 + (grow & 127) * 64;
        int rk = grow & 7;
        #pragma unroll
        for (int nt = 0; nt < 4; nt++) {
            int ci = ((h & 1) * 4 + nt) ^ rk;
            *(uint32_t*)&o[base + ci * 8 + 2 * t] =
                packbf(oa[nt][0] * inv0, oa[nt][1] * inv0);
        }
    }
    if (r1 < L77) {
        int grow = rowmap(wi, r1);
        size_t base = ((size_t)((grow >> 7) * 4 + (h >> 1))) * 8192 + (grow & 127) * 64;
        int rk = grow & 7;
        #pragma unroll
        for (int nt = 0; nt < 4; nt++) {
            int ci = ((h & 1) * 4 + nt) ^ rk;
            *(uint32_t*)&o[base + ci * 8 + 2 * t] =
                packbf(oa[nt][2] * inv1, oa[nt][3] * inv1);
        }
    }
}

// ---------------------------------------------------------------------------
// Launch
// ---------------------------------------------------------------------------
extern "C" void kernel_launch(void* const* d_in, const int* in_sizes, int n_in,
                              void* d_out, int out_size)
{
    const float* x         = (const float*)d_in[0];
    const float* norm1_g   = (const float*)d_in[1];
    const float* norm1_b   = (const float*)d_in[2];
    const float* in_proj_w = (const float*)d_in[3];
    const float* in_proj_b = (const float*)d_in[4];
    const float* out_w     = (const float*)d_in[5];
    const float* out_b     = (const float*)d_in[6];
    const float* norm2_g   = (const float*)d_in[7];
    const float* norm2_b   = (const float*)d_in[8];
    const float* fc1_w     = (const float*)d_in[9];
    const float* fc1_b     = (const float*)d_in[10];
    const float* fc2_w     = (const float*)d_in[11];
    const float* fc2_b     = (const float*)d_in[12];
    float* out = (float*)d_out;

    __nv_bfloat16 *p_xnb, *p_qkvb, *p_wqkv, *p_wout, *p_wfc1, *p_wfc2;
    float* p_y;
    cudaGetSymbolAddress((void**)&p_xnb,  g_xnb);
    cudaGetSymbolAddress((void**)&p_qkvb, g_qkvb);
    cudaGetSymbolAddress((void**)&p_y,    g_y);
    cudaGetSymbolAddress((void**)&p_wqkv, g_wqkv);
    cudaGetSymbolAddress((void**)&p_wout, g_wout);
    cudaGetSymbolAddress((void**)&p_wfc1, g_wfc1);
    cudaGetSymbolAddress((void**)&p_wfc2, g_wfc2);

    cudaFuncSetAttribute((const void*)bgemm_kernel<0, 1, 256, 0, 0>,
                         cudaFuncAttributeMaxDynamicSharedMemorySize, BGSMEM);
    cudaFuncSetAttribute((const void*)bgemm_kernel<2, 0, 256, 0, 0>,
                         cudaFuncAttributeMaxDynamicSharedMemorySize, BGSMEM);
    cudaFuncSetAttribute((const void*)bgemm_kernel<1, 1, 256, 1, 8>,
                         cudaFuncAttributeMaxDynamicSharedMemorySize, BGSMEM);
    cudaFuncSetAttribute((const void*)bgemm_kernel<2, 0, 512, 0, 0>,
                         cudaFuncAttributeMaxDynamicSharedMemorySize, BGSMEM);

    // 0+1) weights -> tiled bf16 images AND LN1 (merged, one launch)
    prep_kernel<<<256 + MROWS / 8, 256>>>(x, norm1_g, norm1_b, p_xnb,
                                          in_proj_w, out_w, fc1_w, fc2_w,
                                          p_wqkv, p_wout, p_wfc1, p_wfc2);

    // 2) QKV = xn @ Wqkv^T + b  (row-major bf16)
    {
        dim3 grid(768 / 128, MROWS / 128);
        bgemm_kernel<0, 1, 256, 0, 0><<<grid, 256, BGSMEM>>>(
            p_xnb, p_wqkv, in_proj_b, nullptr, p_qkvb, MROWS, 3 * Dc);
    }

    // 3) attention -> o image (reuse g_xnb)
    attn_kernel<<<NWIN * HEADS, 160>>>(p_qkvb, p_xnb);

    // 4) y = x + o @ Wout^T + b  (fp32 row-major)
    {
        dim3 grid(Dc / 128, MROWS / 128);
        bgemm_kernel<2, 0, 256, 0, 0><<<grid, 256, BGSMEM>>>(
            p_xnb, p_wout, out_b, x, p_y, MROWS, Dc);
    }

    // 5) LN2: y -> yn image (into g_qkvb[0 : M*256))
    ln_bf_kernel<<<MROWS / 8, 256>>>(p_y, norm2_g, norm2_b, p_qkvb);

    // 6) hmid = gelu(yn @ Wfc1^T + b)  (tiled image, OKT=8)
    __nv_bfloat16* p_yn   = p_qkvb;
    __nv_bfloat16* p_hmid = p_qkvb + (size_t)MROWS * Dc;
    {
        dim3 grid(HIDc / 128, MROWS / 128);
        bgemm_kernel<1, 1, 256, 1, 8><<<grid, 256, BGSMEM>>>(
            p_yn, p_wfc1, fc1_b, nullptr, p_hmid, MROWS, HIDc);
    }

    // 7) out = y + hmid @ Wfc2^T + b  (fp32 row-major)
    {
        dim3 grid(Dc / 128, MROWS / 128);
        bgemm_kernel<2, 0, 512, 0, 0><<<grid, 256, BGSMEM>>>(
            p_hmid, p_wfc2, fc2_b, p_y, out, MROWS, Dc);
    }
}

// round 11
// speedup vs baseline: 3.5008x; 1.0663x over previous
#include <cuda_runtime.h>
#include <cuda_bf16.h>
#include <math.h>
#include <stdint.h>

// Problem constants
#define Bc    8
#define Nc    9856
#define Dc    256
#define HEADS 8
#define HD    32
#define WH    7
#define WW    11
#define L77   77
#define HIDc  512
#define Hc    56
#define Wc    176
#define NH    8
#define NWn   16
#define MROWS (Bc * Nc)       // 78848
#define NWIN  (Bc * NH * NWn) // 1024

// Tiled image layout: tile (rb=r/128, kt=k/64) is an 8192-elem (16 KB) block at
// ((rb*(K/64))+kt)*8192; row r%128 = 64 elems (128 B); 16B chunk c at (c ^ (row&7)).

// ---------------------------------------------------------------------------
// Scratch (device globals)
// ---------------------------------------------------------------------------
__device__ __nv_bfloat16 g_xnb[(size_t)MROWS * Dc];        // xn image; later o image
__device__ __nv_bfloat16 g_qkvb[(size_t)MROWS * 3 * Dc];   // qkv row-major; later [yn img | hmid img]
__device__ float         g_y[(size_t)MROWS * Dc];          // x + attn residual
__device__ __nv_bfloat16 g_wqkv[3 * Dc * Dc];
__device__ __nv_bfloat16 g_wout[Dc * Dc];
__device__ __nv_bfloat16 g_wfc1[HIDc * Dc];
__device__ __nv_bfloat16 g_wfc2[Dc * HIDc];

// ---------------------------------------------------------------------------
// helpers
// ---------------------------------------------------------------------------
__device__ __forceinline__ uint32_t packbf(float a, float b)
{
    union { __nv_bfloat162 h; uint32_t u; } p;
    p.h = __float22bfloat162_rn(make_float2(a, b));
    return p.u;
}

__device__ __forceinline__ void ldsm4(uint32_t* r, uint32_t addr)
{
    asm volatile("ldmatrix.sync.aligned.m8n8.x4.shared.b16 {%0,%1,%2,%3}, [%4];"
                 : "=r"(r[0]), "=r"(r[1]), "=r"(r[2]), "=r"(r[3]) : "r"(addr));
}

__device__ __forceinline__ void ldsm4t(uint32_t* r, uint32_t addr)
{
    asm volatile("ldmatrix.sync.aligned.m8n8.x4.trans.shared.b16 {%0,%1,%2,%3}, [%4];"
                 : "=r"(r[0]), "=r"(r[1]), "=r"(r[2]), "=r"(r[3]) : "r"(addr));
}

__device__ __forceinline__ void mma_bf16(float (&c)[4], const uint32_t* a,
                                         uint32_t b0, uint32_t b1)
{
    asm volatile(
        "mma.sync.aligned.m16n8k16.row.col.f32.bf16.bf16.f32 "
        "{%0,%1,%2,%3}, {%4,%5,%6,%7}, {%8,%9}, {%0,%1,%2,%3};"
        : "+f"(c[0]), "+f"(c[1]), "+f"(c[2]), "+f"(c[3])
        : "r"(a[0]), "r"(a[1]), "r"(a[2]), "r"(a[3]), "r"(b0), "r"(b1));
}

__device__ __forceinline__ float gelu_exact(float v)
{
    return 0.5f * v * (1.0f + erff(v * 0.70710678118654752f));
}

__device__ __forceinline__ void mbar_init(uint32_t a, uint32_t cnt)
{
    asm volatile("mbarrier.init.shared.b64 [%0], %1;" :: "r"(a), "r"(cnt) : "memory");
}
__device__ __forceinline__ void mbar_expect_tx(uint32_t a, uint32_t bytes)
{
    asm volatile("mbarrier.arrive.expect_tx.shared.b64 _, [%0], %1;"
                 :: "r"(a), "r"(bytes) : "memory");
}
__device__ __forceinline__ void mbar_arrive(uint32_t a)
{
    asm volatile("mbarrier.arrive.shared.b64 _, [%0];" :: "r"(a) : "memory");
}
__device__ __forceinline__ void mbar_wait(uint32_t a, uint32_t ph)
{
    asm volatile(
        "{\n\t.reg .pred P;\n"
        "LW%=:\n\tmbarrier.try_wait.parity.acquire.cta.shared::cta.b64 P, [%0], %1, 0x989680;\n"
        "\t@P bra LD%=;\n\tbra LW%=;\nLD%=:\n\t}"
        :: "r"(a), "r"(ph) : "memory");
}
__device__ __forceinline__ void bulk_g2s(uint32_t dst, const void* src,
                                         uint32_t bytes, uint32_t mbar)
{
    asm volatile(
        "cp.async.bulk.shared::cluster.global.mbarrier::complete_tx::bytes "
        "[%0], [%1], %2, [%3];"
        :: "r"(dst), "l"(src), "r"(bytes), "r"(mbar) : "memory");
}

// ---------------------------------------------------------------------------
// weight conversion helper (fp32 row-major [N,K] -> tiled bf16 image)
// ---------------------------------------------------------------------------
__device__ __forceinline__ void emit_w(const float* __restrict__ src,
                                       __nv_bfloat16* __restrict__ dst,
                                       int i, int Kd)
{
    int n = i / Kd, k = i - n * Kd;
    float4 v0 = *(const float4*)(src + i);
    float4 v1 = *(const float4*)(src + i + 4);
    union { __nv_bfloat162 h[4]; uint4 u; } pk;
    pk.h[0] = __float22bfloat162_rn(make_float2(v0.x, v0.y));
    pk.h[1] = __float22bfloat162_rn(make_float2(v0.z, v0.w));
    pk.h[2] = __float22bfloat162_rn(make_float2(v1.x, v1.y));
    pk.h[3] = __float22bfloat162_rn(make_float2(v1.z, v1.w));
    int KT = Kd >> 6;
    size_t e = ((size_t)((n >> 7) * KT + (k >> 6))) * 8192 + (n & 127) * 64
             + ((((k >> 3) & 7) ^ (n & 7)) << 3);
    *(uint4*)(dst + e) = pk.u;
}

// ---------------------------------------------------------------------------
// LayerNorm body (one warp per row of 256; writes tiled bf16 image, KT=4)
// ---------------------------------------------------------------------------
__device__ __forceinline__ void ln_row(const float* __restrict__ x,
                                       const float* __restrict__ g,
                                       const float* __restrict__ b,
                                       __nv_bfloat16* __restrict__ out,
                                       size_t row, int lane)
{
    const float* xr = x + row * Dc;
    int c = lane * 8;
    float4 v0 = *(const float4*)(xr + c);
    float4 v1 = *(const float4*)(xr + c + 4);
    float sum = v0.x + v0.y + v0.z + v0.w + v1.x + v1.y + v1.z + v1.w;
    float sq  = v0.x*v0.x + v0.y*v0.y + v0.z*v0.z + v0.w*v0.w
              + v1.x*v1.x + v1.y*v1.y + v1.z*v1.z + v1.w*v1.w;
    #pragma unroll
    for (int off = 16; off; off >>= 1) {
        sum += __shfl_xor_sync(0xffffffff, sum, off);
        sq  += __shfl_xor_sync(0xffffffff, sq,  off);
    }
    float mu  = sum * (1.0f / 256.0f);
    float var = sq * (1.0f / 256.0f) - mu * mu;
    float rs  = rsqrtf(var + 1e-5f);
    float4 g0 = *(const float4*)(g + c), g1 = *(const float4*)(g + c + 4);
    float4 b0 = *(const float4*)(b + c), b1 = *(const float4*)(b + c + 4);
    union { __nv_bfloat162 h[4]; uint4 u; } pk;
    pk.h[0] = __float22bfloat162_rn(make_float2((v0.x - mu) * rs * g0.x + b0.x,
                                                (v0.y - mu) * rs * g0.y + b0.y));
    pk.h[1] = __float22bfloat162_rn(make_float2((v0.z - mu) * rs * g0.z + b0.z,
                                                (v0.w - mu) * rs * g0.w + b0.w));
    pk.h[2] = __float22bfloat162_rn(make_float2((v1.x - mu) * rs * g1.x + b1.x,
                                                (v1.y - mu) * rs * g1.y + b1.y));
    pk.h[3] = __float22bfloat162_rn(make_float2((v1.z - mu) * rs * g1.z + b1.z,
                                                (v1.w - mu) * rs * g1.w + b1.w));
    int kt = lane >> 3;
    int cs = (lane & 7) ^ ((int)row & 7);
    size_t e = ((size_t)((row >> 7) * 4 + kt)) * 8192 + (row & 127) * 64 + (cs << 3);
    *(uint4*)(out + e) = pk.u;
}

__global__ void __launch_bounds__(256) ln_bf_kernel(const float* __restrict__ x,
                                                    const float* __restrict__ g,
                                                    const float* __restrict__ b,
                                                    __nv_bfloat16* __restrict__ out)
{
    int warp = threadIdx.x >> 5, lane = threadIdx.x & 31;
    ln_row(x, g, b, out, (size_t)blockIdx.x * 8 + warp, lane);
}

// Merged: blocks [0,256) convert the 4 weight matrices; blocks [256,...) do LN1.
__global__ void __launch_bounds__(256) prep_kernel(const float* __restrict__ x,
                                                   const float* __restrict__ g,
                                                   const float* __restrict__ b,
                                                   __nv_bfloat16* __restrict__ out,
                                                   const float* __restrict__ w0,
                                                   const float* __restrict__ w1,
                                                   const float* __restrict__ w2,
                                                   const float* __restrict__ w3,
                                                   __nv_bfloat16* __restrict__ o0,
                                                   __nv_bfloat16* __restrict__ o1,
                                                   __nv_bfloat16* __restrict__ o2,
                                                   __nv_bfloat16* __restrict__ o3)
{
    if (blockIdx.x < 256) {
        int u = blockIdx.x * 256 + threadIdx.x;
        if (u < 24576)      emit_w(w0, o0, u * 8, 256);
        else if (u < 32768) emit_w(w1, o1, (u - 24576) * 8, 256);
        else if (u < 49152) emit_w(w2, o2, (u - 32768) * 8, 256);
        else                emit_w(w3, o3, (u - 49152) * 8, 512);
        return;
    }
    int warp = threadIdx.x >> 5, lane = threadIdx.x & 31;
    ln_row(x, g, b, out, (size_t)(blockIdx.x - 256) * 8 + warp, lane);
}

// ---------------------------------------------------------------------------
// bf16 GEMM on tiled images: CTA 128x128, BK=64, 3-stage bulk ring.
// Producer/consumer mbarriers: data[s] (tx-count) + empty[s] (8 warp arrivals).
// No per-K-tile __syncthreads — consumers stream; only warp 0 waits to recycle.
// ---------------------------------------------------------------------------
#define BGSMEM (3 * 32768)

template <int EPI, int OBF, int K, int OTILED, int OKT>
__global__ void __launch_bounds__(256, 2) bgemm_kernel(const __nv_bfloat16* __restrict__ Aimg,
                                                       const __nv_bfloat16* __restrict__ Bimg,
                                                       const float* __restrict__ bias,
                                                       const float* __restrict__ resid,
                                                       void* __restrict__ Cv,
                                                       int M, int N)
{
    extern __shared__ __nv_bfloat16 dyn[];
    __shared__ uint64_t mbar_s[6];   // [0..2]=data, [3..5]=empty

    constexpr int KT = K >> 6;
    int tid = threadIdx.x, lane = tid & 31, warp = tid >> 5;
    int wm = warp >> 2, wn = warp & 3;
    int m0 = blockIdx.y * 128, n0 = blockIdx.x * 128;

    uint32_t sbase = (uint32_t)__cvta_generic_to_shared(dyn);
    uint32_t mbD = (uint32_t)__cvta_generic_to_shared(&mbar_s[0]);
    uint32_t mbE = mbD + 24;

    const __nv_bfloat16* Asrc = Aimg + (size_t)blockIdx.y * KT * 8192;
    const __nv_bfloat16* Bsrc = Bimg + (size_t)blockIdx.x * KT * 8192;

    if (tid == 0) {
        #pragma unroll
        for (int s = 0; s < 3; s++) {
            mbar_init(mbD + s * 8, 1);
            mbar_init(mbE + s * 8, 8);   // one arrive per warp
        }
    }
    __syncthreads();
    if (tid == 0) {
        #pragma unroll
        for (int s = 0; s < 3 && s < KT; s++) {
            mbar_expect_tx(mbD + s * 8, 32768);
            bulk_g2s(sbase + s * 32768,         Asrc + s * 8192, 16384, mbD + s * 8);
            bulk_g2s(sbase + s * 32768 + 16384, Bsrc + s * 8192, 16384, mbD + s * 8);
        }
    }

    int ac = lane >> 4;            // A chunk select
    int br = (lane & 7) | (((lane >> 4) & 1) << 3);
    int bc = (lane >> 3) & 1;      // B chunk select
    int sk = lane & 7;
    uint32_t aRow[4], bRow[2];
    #pragma unroll
    for (int mt = 0; mt < 4; mt++)
        aRow[mt] = (wm * 64 + mt * 16 + (lane & 15)) * 128;
    #pragma unroll
    for (int p = 0; p < 2; p++)
        bRow[p] = (wn * 32 + p * 16 + br) * 128;

    float acc[4][4][4] = {};

    #pragma unroll
    for (int kt = 0; kt < KT; kt++) {
        const int s = kt % 3;
        const uint32_t ph = (kt / 3) & 1;
        mbar_wait(mbD + s * 8, ph);
        uint32_t aB = sbase + s * 32768;
        uint32_t bB = aB + 16384;
        #pragma unroll
        for (int kk = 0; kk < 4; kk++) {
            uint32_t ca = (uint32_t)(((kk * 2 + ac) ^ sk) << 4);
            uint32_t cb = (uint32_t)(((kk * 2 + bc) ^ sk) << 4);
            uint32_t a[4][4], b[2][4];
            #pragma unroll
            for (int mt = 0; mt < 4; mt++)
                ldsm4(a[mt], aB + aRow[mt] + ca);
            #pragma unroll
            for (int p = 0; p < 2; p++)
                ldsm4(b[p], bB + bRow[p] + cb);
            #pragma unroll
            for (int mt = 0; mt < 4; mt++) {
                mma_bf16(acc[mt][0], a[mt], b[0][0], b[0][1]);
                mma_bf16(acc[mt][1], a[mt], b[0][2], b[0][3]);
                mma_bf16(acc[mt][2], a[mt], b[1][0], b[1][1]);
                mma_bf16(acc[mt][3], a[mt], b[1][2], b[1][3]);
            }
        }
        // consumer arrive: this warp is done reading stage s
        if (lane == 0) mbar_arrive(mbE + s * 8);
        // producer (warp 0, converged): recycle stage s for kt+3
        if (warp == 0 && kt + 3 < KT) {
            mbar_wait(mbE + s * 8, ph);
            if (lane == 0) {
                mbar_expect_tx(mbD + s * 8, 32768);
                bulk_g2s(sbase + s * 32768,         Asrc + (kt + 3) * 8192, 16384, mbD + s * 8);
                bulk_g2s(sbase + s * 32768 + 16384, Bsrc + (kt + 3) * 8192, 16384, mbD + s * 8);
            }
        }
    }

    float* Cf = (float*)Cv;
    __nv_bfloat16* Cb = (__nv_bfloat16*)Cv;
    int g = lane >> 2, t = lane & 3;
    #pragma unroll
    for (int mt = 0; mt < 4; mt++) {
        size_t r0 = (size_t)m0 + wm * 64 + mt * 16 + g;
        size_t r1 = r0 + 8;
        #pragma unroll
        for (int nt = 0; nt < 4; nt++) {
            int col = n0 + wn * 32 + nt * 8 + 2 * t;
            float b0 = bias[col], b1 = bias[col + 1];
            float v00 = acc[mt][nt][0] + b0, v01 = acc[mt][nt][1] + b1;
            float v10 = acc[mt][nt][2] + b0, v11 = acc[mt][nt][3] + b1;
            if (EPI == 1) {
                v00 = gelu_exact(v00); v01 = gelu_exact(v01);
                v10 = gelu_exact(v10); v11 = gelu_exact(v11);
            }
            if (EPI == 2) {
                float2 q0 = *(const float2*)&resid[r0 * N + col];
                float2 q1 = *(const float2*)&resid[r1 * N + col];
                v00 += q0.x; v01 += q0.y; v10 += q1.x; v11 += q1.y;
            }
            if (OTILED) {
                int kto = col >> 6;
                int ci  = (col >> 3) & 7;
                size_t e0 = ((size_t)((r0 >> 7) * OKT + kto)) * 8192 + (r0 & 127) * 64
                          + (((size_t)(ci ^ ((int)r0 & 7))) << 3) + (col & 7);
                size_t e1 = ((size_t)((r1 >> 7) * OKT + kto)) * 8192 + (r1 & 127) * 64
                          + (((size_t)(ci ^ ((int)r1 & 7))) << 3) + (col & 7);
                *(uint32_t*)&Cb[e0] = packbf(v00, v01);
                *(uint32_t*)&Cb[e1] = packbf(v10, v11);
            } else if (OBF) {
                *(uint32_t*)&Cb[r0 * N + col] = packbf(v00, v01);
                *(uint32_t*)&Cb[r1 * N + col] = packbf(v10, v11);
            } else {
                *(float2*)&Cf[r0 * N + col] = make_float2(v00, v01);
                *(float2*)&Cf[r1 * N + col] = make_float2(v10, v11);
            }
        }
    }
}

// ---------------------------------------------------------------------------
// Windowed attention (bf16 mma.sync) — unchanged from R10
// ---------------------------------------------------------------------------
__device__ __forceinline__ int rowmap(int wi, int l)
{
    int b   = wi >> 7;
    int rem = wi & 127;
    int hb  = rem >> 4;
    int wb  = rem & 15;
    int r   = l / WW;
    int c   = l - r * WW;
    return b * Nc + (hb * WH + r) * Wc + wb * WW + c;
}

__global__ void __launch_bounds__(160) attn_kernel(const __nv_bfloat16* __restrict__ qkv,
                                                   __nv_bfloat16* __restrict__ o)
{
    __shared__ __nv_bfloat16 sQ[80 * 40];
    __shared__ __nv_bfloat16 sK[80 * 40];
    __shared__ __nv_bfloat16 sV[80 * 40];

    int bx = blockIdx.x, wi = bx >> 3, h = bx & 7;
    int tid = threadIdx.x, lane = tid & 31, w = tid >> 5;

    int lrow = tid >> 2, lseg = tid & 3;
    #pragma unroll
    for (int r0 = 0; r0 < 80; r0 += 40) {
        int l = r0 + lrow;
        uint4 qv = make_uint4(0, 0, 0, 0), kv = qv, vv = qv;
        if (l < L77) {
            int grow = rowmap(wi, l);
            const __nv_bfloat16* base = qkv + (size_t)grow * (3 * Dc) + h * HD + lseg * 8;
            qv = *(const uint4*)(base);
            kv = *(const uint4*)(base + Dc);
            vv = *(const uint4*)(base + 2 * Dc);
        }
        *(uint4*)&sQ[l * 40 + lseg * 8] = qv;
        *(uint4*)&sK[l * 40 + lseg * 8] = kv;
        *(uint4*)&sV[l * 40 + lseg * 8] = vv;
    }
    __syncthreads();

    int a_row = lane & 15;
    int a_c   = lane >> 4;
    int b_row = (lane & 7) | (((lane >> 4) & 1) << 3);
    int b_c   = (lane >> 3) & 1;
    int g = lane >> 2, t = lane & 3;

    uint32_t aQ = (uint32_t)__cvta_generic_to_shared(&sQ[(w * 16 + a_row) * 40]) + a_c * 16;
    uint32_t bK = (uint32_t)__cvta_generic_to_shared(&sK[b_row * 40]) + b_c * 16;
    uint32_t bV = (uint32_t)__cvta_generic_to_shared(sV)
                + ((lane & 15) * 40 + ((lane >> 4) << 3)) * 2;

    float s[10][4] = {};
    uint32_t aq[2][4];
    ldsm4(aq[0], aQ);
    ldsm4(aq[1], aQ + 32);
    #pragma unroll
    for (int kk = 0; kk < 2; kk++) {
        #pragma unroll
        for (int p = 0; p < 5; p++) {
            uint32_t b[4];
            ldsm4(b, bK + p * 1280 + kk * 32);
            mma_bf16(s[2 * p],     aq[kk], b[0], b[1]);
            mma_bf16(s[2 * p + 1], aq[kk], b[2], b[3]);
        }
    }

    if (72 + 2 * t >= L77) { s[9][0] = -1e30f; s[9][2] = -1e30f; }
    if (73 + 2 * t >= L77) { s[9][1] = -1e30f; s[9][3] = -1e30f; }

    const float scale = 0.17677669529663687f;
    float mx0 = -1e30f, mx1 = -1e30f;
    #pragma unroll
    for (int nt = 0; nt < 10; nt++) {
        mx0 = fmaxf(mx0, fmaxf(s[nt][0], s[nt][1]));
        mx1 = fmaxf(mx1, fmaxf(s[nt][2], s[nt][3]));
    }
    mx0 = fmaxf(mx0, __shfl_xor_sync(0xffffffff, mx0, 1));
    mx0 = fmaxf(mx0, __shfl_xor_sync(0xffffffff, mx0, 2));
    mx1 = fmaxf(mx1, __shfl_xor_sync(0xffffffff, mx1, 1));
    mx1 = fmaxf(mx1, __shfl_xor_sync(0xffffffff, mx1, 2));
    float ms0 = mx0 * scale, ms1 = mx1 * scale;

    float e[10][4];
    float sum0 = 0.f, sum1 = 0.f;
    #pragma unroll
    for (int nt = 0; nt < 10; nt++) {
        e[nt][0] = __expf(fmaf(s[nt][0], scale, -ms0));
        e[nt][1] = __expf(fmaf(s[nt][1], scale, -ms0));
        e[nt][2] = __expf(fmaf(s[nt][2], scale, -ms1));
        e[nt][3] = __expf(fmaf(s[nt][3], scale, -ms1));
        sum0 += e[nt][0] + e[nt][1];
        sum1 += e[nt][2] + e[nt][3];
    }
    sum0 += __shfl_xor_sync(0xffffffff, sum0, 1);
    sum0 += __shfl_xor_sync(0xffffffff, sum0, 2);
    sum1 += __shfl_xor_sync(0xffffffff, sum1, 1);
    sum1 += __shfl_xor_sync(0xffffffff, sum1, 2);
    float inv0 = 1.0f / sum0, inv1 = 1.0f / sum1;

    uint32_t pa[5][4];
    #pragma unroll
    for (int kf = 0; kf < 5; kf++) {
        pa[kf][0] = packbf(e[2 * kf][0],     e[2 * kf][1]);
        pa[kf][1] = packbf(e[2 * kf][2],     e[2 * kf][3]);
        pa[kf][2] = packbf(e[2 * kf + 1][0], e[2 * kf + 1][1]);
        pa[kf][3] = packbf(e[2 * kf + 1][2], e[2 * kf + 1][3]);
    }

    float oa[4][4] = {};
    #pragma unroll
    for (int kf = 0; kf < 5; kf++) {
        #pragma unroll
        for (int vt = 0; vt < 2; vt++) {
            uint32_t b[4];
            ldsm4t(b, bV + (kf * 16 * 40 + vt * 16) * 2);
            mma_bf16(oa[2 * vt],     pa[kf], b[0], b[1]);
            mma_bf16(oa[2 * vt + 1], pa[kf], b[2], b[3]);
        }
    }

    int r0 = w * 16 + g, r1 = r0 + 8;
    if (r0 < L77) {
        int grow = rowmap(wi, r0);
        size_t base = ((size_t)((grow >> 7) * 4 + (h >> 1))) * 8192 + (grow & 127) * 64;
        int rk = grow & 7;
        #pragma unroll
        for (int nt = 0; nt < 4; nt++) {
            int ci = ((h & 1) * 4 + nt) ^ rk;
            *(uint32_t*)&o[base + ci * 8 + 2 * t] =
                packbf(oa[nt][0] * inv0, oa[nt][1] * inv0);
        }
    }
    if (r1 < L77) {
        int grow = rowmap(wi, r1);
        size_t base = ((size_t)((grow >> 7) * 4 + (h >> 1))) * 8192 + (grow & 127) * 64;
        int rk = grow & 7;
        #pragma unroll
        for (int nt = 0; nt < 4; nt++) {
            int ci = ((h & 1) * 4 + nt) ^ rk;
            *(uint32_t*)&o[base + ci * 8 + 2 * t] =
                packbf(oa[nt][2] * inv1, oa[nt][3] * inv1);
        }
    }
}

// ---------------------------------------------------------------------------
// Launch
// ---------------------------------------------------------------------------
extern "C" void kernel_launch(void* const* d_in, const int* in_sizes, int n_in,
                              void* d_out, int out_size)
{
    const float* x         = (const float*)d_in[0];
    const float* norm1_g   = (const float*)d_in[1];
    const float* norm1_b   = (const float*)d_in[2];
    const float* in_proj_w = (const float*)d_in[3];
    const float* in_proj_b = (const float*)d_in[4];
    const float* out_w     = (const float*)d_in[5];
    const float* out_b     = (const float*)d_in[6];
    const float* norm2_g   = (const float*)d_in[7];
    const float* norm2_b   = (const float*)d_in[8];
    const float* fc1_w     = (const float*)d_in[9];
    const float* fc1_b     = (const float*)d_in[10];
    const float* fc2_w     = (const float*)d_in[11];
    const float* fc2_b     = (const float*)d_in[12];
    float* out = (float*)d_out;

    __nv_bfloat16 *p_xnb, *p_qkvb, *p_wqkv, *p_wout, *p_wfc1, *p_wfc2;
    float* p_y;
    cudaGetSymbolAddress((void**)&p_xnb,  g_xnb);
    cudaGetSymbolAddress((void**)&p_qkvb, g_qkvb);
    cudaGetSymbolAddress((void**)&p_y,    g_y);
    cudaGetSymbolAddress((void**)&p_wqkv, g_wqkv);
    cudaGetSymbolAddress((void**)&p_wout, g_wout);
    cudaGetSymbolAddress((void**)&p_wfc1, g_wfc1);
    cudaGetSymbolAddress((void**)&p_wfc2, g_wfc2);

    cudaFuncSetAttribute((const void*)bgemm_kernel<0, 1, 256, 0, 0>,
                         cudaFuncAttributeMaxDynamicSharedMemorySize, BGSMEM);
    cudaFuncSetAttribute((const void*)bgemm_kernel<2, 0, 256, 0, 0>,
                         cudaFuncAttributeMaxDynamicSharedMemorySize, BGSMEM);
    cudaFuncSetAttribute((const void*)bgemm_kernel<1, 1, 256, 1, 8>,
                         cudaFuncAttributeMaxDynamicSharedMemorySize, BGSMEM);
    cudaFuncSetAttribute((const void*)bgemm_kernel<2, 0, 512, 0, 0>,
                         cudaFuncAttributeMaxDynamicSharedMemorySize, BGSMEM);

    // 0+1) weights -> tiled bf16 images AND LN1 (merged)
    prep_kernel<<<256 + MROWS / 8, 256>>>(x, norm1_g, norm1_b, p_xnb,
                                          in_proj_w, out_w, fc1_w, fc2_w,
                                          p_wqkv, p_wout, p_wfc1, p_wfc2);

    // 2) QKV = xn @ Wqkv^T + b  (row-major bf16)
    {
        dim3 grid(768 / 128, MROWS / 128);
        bgemm_kernel<0, 1, 256, 0, 0><<<grid, 256, BGSMEM>>>(
            p_xnb, p_wqkv, in_proj_b, nullptr, p_qkvb, MROWS, 3 * Dc);
    }

    // 3) attention -> o image (reuse g_xnb)
    attn_kernel<<<NWIN * HEADS, 160>>>(p_qkvb, p_xnb);

    // 4) y = x + o @ Wout^T + b  (fp32 row-major)
    {
        dim3 grid(Dc / 128, MROWS / 128);
        bgemm_kernel<2, 0, 256, 0, 0><<<grid, 256, BGSMEM>>>(
            p_xnb, p_wout, out_b, x, p_y, MROWS, Dc);
    }

    // 5) LN2: y -> yn image (into g_qkvb[0 : M*256))
    ln_bf_kernel<<<MROWS / 8, 256>>>(p_y, norm2_g, norm2_b, p_qkvb);

    // 6) hmid = gelu(yn @ Wfc1^T + b)  (tiled image, OKT=8)
    __nv_bfloat16* p_yn   = p_qkvb;
    __nv_bfloat16* p_hmid = p_qkvb + (size_t)MROWS * Dc;
    {
        dim3 grid(HIDc / 128, MROWS / 128);
        bgemm_kernel<1, 1, 256, 1, 8><<<grid, 256, BGSMEM>>>(
            p_yn, p_wfc1, fc1_b, nullptr, p_hmid, MROWS, HIDc);
    }

    // 7) out = y + hmid @ Wfc2^T + b  (fp32 row-major)
    {
        dim3 grid(Dc / 128, MROWS / 128);
        bgemm_kernel<2, 0, 512, 0, 0><<<grid, 256, BGSMEM>>>(
            p_hmid, p_wfc2, fc2_b, p_y, out, MROWS, Dc);
    }
}